// round 11
// baseline (speedup 1.0000x reference)
#include <cuda_runtime.h>
#include <cuda_bf16.h>
#include <math.h>
#include <stdint.h>

// Problem constants
#define VV 32000
#define EE 512
#define HH 1024
#define BB 32
#define TT 64
#define G4H (4 * HH)          // 4096
#define NROWS (BB * TT)       // 2048

#define NBLK 128              // persistent blocks (each owns 8 hcols x 4 gates)
#define NTHR 256              // 8 warps (big reg budget for U fragments)

// smem word-layout (32-bit words)
#define HROW 516              // h row stride: [m][516] (512 packed-pair words + 4 pad)
#define UBROW 260             // U init-chunk row stride (256 words + 4 pad)
#define ZROW 1156             // per-warp z partial stride (32*36 + 4)
#define SCAN_SMEM_WORDS (2*32*HROW + 8*ZROW)
#define SCAN_SMEM_BYTES (SCAN_SMEM_WORDS * 4)   // 169,088 B

// ---------------- scratch (no allocs allowed) ----------------
__device__ float    g_xW[NROWS * G4H];     // [b*T+t, 4H] input projections (+bias)
__device__ float    g_seq[NROWS * HH];     // [b*T+t, H] hidden states (tf32-pre-rounded)
__device__ float    g_h[2][BB * HH];       // final-h staging (scan writes at t=63)
__device__ float    g_c[BB * HH];          // cell state
__device__ int      g_flag[NBLK];          // per-block step flags
__device__ uint32_t g_hbf[2][2][32][512];  // packed bf16 h pairs [buf][hi/lo][m][kpair]
__device__ float    g_Bh[(size_t)HH * VV]; // dense_W tf32 hi part
__device__ float    g_Bl[(size_t)HH * VV]; // dense_W tf32 lo part

// ---------------- bf16 helpers ----------------
__device__ __forceinline__ uint32_t packbf2(float a, float b) {  // a -> low half (first k)
    __nv_bfloat162 p = __floats2bfloat162_rn(a, b);
    return *reinterpret_cast<uint32_t*>(&p);
}
__device__ __forceinline__ float bfhi(float x) {
    return __bfloat162float(__float2bfloat16_rn(x));
}

__device__ __forceinline__ void mma_bf16(float* c, uint32_t a0, uint32_t a1, uint32_t a2, uint32_t a3,
                                         uint32_t b0, uint32_t b1) {
    asm volatile(
        "mma.sync.aligned.m16n8k16.row.col.f32.bf16.bf16.f32 "
        "{%0,%1,%2,%3}, {%4,%5,%6,%7}, {%8,%9}, {%0,%1,%2,%3};"
        : "+f"(c[0]), "+f"(c[1]), "+f"(c[2]), "+f"(c[3])
        : "r"(a0), "r"(a1), "r"(a2), "r"(a3), "r"(b0), "r"(b1));
}

// ---------------- tf32 helpers ----------------
__device__ __forceinline__ float to_tf32(float x) {
    uint32_t y;
    asm("cvt.rna.tf32.f32 %0, %1;" : "=r"(y) : "f"(x));
    return __uint_as_float(y);
}

__device__ __forceinline__ void mma_tf32(float* c, uint32_t a0, uint32_t a1, uint32_t a2, uint32_t a3,
                                         uint32_t b0, uint32_t b1) {
    asm volatile(
        "mma.sync.aligned.m16n8k8.row.col.f32.tf32.tf32.f32 "
        "{%0,%1,%2,%3}, {%4,%5,%6,%7}, {%8,%9}, {%0,%1,%2,%3};"
        : "+f"(c[0]), "+f"(c[1]), "+f"(c[2]), "+f"(c[3])
        : "r"(a0), "r"(a1), "r"(a2), "r"(a3), "r"(b0), "r"(b1));
}

// ---------------- init / finalize ----------------
__global__ void init_state_kernel(const float* __restrict__ h0, const float* __restrict__ c0) {
    int i = blockIdx.x * blockDim.x + threadIdx.x;
    if (i < BB * HH) g_c[i] = c0[i];
    if (i < BB * HH / 2) {                 // pack h0 into g_hbf[0]
        int m = i >> 9;
        int kp = i & 511;
        float a = h0[m * HH + 2 * kp];
        float b = h0[m * HH + 2 * kp + 1];
        float ah = bfhi(a), bh = bfhi(b);
        g_hbf[0][0][m][kp] = packbf2(ah, bh);
        g_hbf[0][1][m][kp] = packbf2(a - ah, b - bh);
    }
    if (i < NBLK) g_flag[i] = 0;
}

__global__ void write_state_kernel(float* __restrict__ out_h, float* __restrict__ out_c) {
    int i = blockIdx.x * blockDim.x + threadIdx.x;
    if (i < BB * HH) {
        out_h[i] = g_h[0][i];
        out_c[i] = g_c[i];
    }
}

// ---------------- B hi/lo pre-split (dense_W) ----------------
__global__ void split_b_kernel(const float* __restrict__ B) {
    const size_t n4 = (size_t)HH * VV / 4;
    size_t i = (size_t)blockIdx.x * blockDim.x + threadIdx.x;
    const size_t stride = (size_t)gridDim.x * blockDim.x;
    const float4* B4 = (const float4*)B;
    float4* H4 = (float4*)g_Bh;
    float4* L4 = (float4*)g_Bl;
    for (; i < n4; i += stride) {
        float4 v = B4[i];
        float4 h, l;
        h.x = to_tf32(v.x); l.x = to_tf32(v.x - h.x);
        h.y = to_tf32(v.y); l.y = to_tf32(v.y - h.y);
        h.z = to_tf32(v.z); l.z = to_tf32(v.z - h.z);
        h.w = to_tf32(v.w); l.w = to_tf32(v.w - h.w);
        H4[i] = h;
        L4[i] = l;
    }
}

// ---------------- tf32x2 GEMM (logits) ----------------
__global__ __launch_bounds__(256, 1)
void tf32_gemm_kernel(const float* __restrict__ A,
                      const float* __restrict__ Bhi, const float* __restrict__ Blo,
                      const float* __restrict__ bias, float* __restrict__ C,
                      int M, int N, int K)
{
    __shared__ float As[128][20];
    __shared__ float Bh[16][136];
    __shared__ float Bl[16][136];

    const int tid = threadIdx.x;
    const int lane = tid & 31;
    const int wid = tid >> 5;
    const int wr = wid >> 2;
    const int wc = wid & 3;
    const int bm = blockIdx.y * 128;
    const int bn = blockIdx.x * 128;

    float acc[4][4][4];
#pragma unroll
    for (int i = 0; i < 4; ++i)
#pragma unroll
        for (int j = 0; j < 4; ++j)
#pragma unroll
            for (int r = 0; r < 4; ++r) acc[i][j][r] = 0.f;

    float4 pa[2], pbh[2], pbl[2];
#pragma unroll
    for (int i = 0; i < 2; ++i) {
        int id = tid + i * 256;
        int m = id >> 2, kq = (id & 3) * 4;
        pa[i] = *(const float4*)(A + (size_t)(bm + m) * K + kq);
        int k = id >> 5, n4 = (id & 31) * 4;
        pbh[i] = *(const float4*)(Bhi + (size_t)k * N + bn + n4);
        pbl[i] = *(const float4*)(Blo + (size_t)k * N + bn + n4);
    }

    for (int kt = 0; kt < K; kt += 16) {
#pragma unroll
        for (int i = 0; i < 2; ++i) {
            int id = tid + i * 256;
            int m = id >> 2, kq = (id & 3) * 4;
            *(float4*)(&As[m][kq]) = pa[i];
            int k = id >> 5, n4 = (id & 31) * 4;
            *(float4*)(&Bh[k][n4]) = pbh[i];
            *(float4*)(&Bl[k][n4]) = pbl[i];
        }
        __syncthreads();

        if (kt + 16 < K) {
#pragma unroll
            for (int i = 0; i < 2; ++i) {
                int id = tid + i * 256;
                int m = id >> 2, kq = (id & 3) * 4;
                pa[i] = *(const float4*)(A + (size_t)(bm + m) * K + kt + 16 + kq);
                int k = id >> 5, n4 = (id & 31) * 4;
                pbh[i] = *(const float4*)(Bhi + (size_t)(kt + 16 + k) * N + bn + n4);
                pbl[i] = *(const float4*)(Blo + (size_t)(kt + 16 + k) * N + bn + n4);
            }
        }

#pragma unroll
        for (int ks = 0; ks < 16; ks += 8) {
            uint32_t af[4][4];
#pragma unroll
            for (int mt = 0; mt < 4; ++mt) {
                int r0 = wr * 64 + mt * 16 + (lane >> 2);
                int kc = ks + (lane & 3);
                af[mt][0] = __float_as_uint(As[r0][kc]);
                af[mt][1] = __float_as_uint(As[r0 + 8][kc]);
                af[mt][2] = __float_as_uint(As[r0][kc + 4]);
                af[mt][3] = __float_as_uint(As[r0 + 8][kc + 4]);
            }
#pragma unroll
            for (int nt = 0; nt < 4; ++nt) {
                int c0 = wc * 32 + nt * 8 + (lane >> 2);
                int kc = ks + (lane & 3);
                uint32_t bh0 = __float_as_uint(Bh[kc][c0]);
                uint32_t bh1 = __float_as_uint(Bh[kc + 4][c0]);
                uint32_t bl0 = __float_as_uint(Bl[kc][c0]);
                uint32_t bl1 = __float_as_uint(Bl[kc + 4][c0]);
#pragma unroll
                for (int mt = 0; mt < 4; ++mt) {
                    mma_tf32(acc[mt][nt], af[mt][0], af[mt][1], af[mt][2], af[mt][3], bh0, bh1);
                    mma_tf32(acc[mt][nt], af[mt][0], af[mt][1], af[mt][2], af[mt][3], bl0, bl1);
                }
            }
        }
        __syncthreads();
    }

#pragma unroll
    for (int mt = 0; mt < 4; ++mt) {
        int r0 = bm + wr * 64 + mt * 16 + (lane >> 2);
#pragma unroll
        for (int nt = 0; nt < 4; ++nt) {
            int col = bn + wc * 32 + nt * 8 + 2 * (lane & 3);
            float b0 = bias[col], b1 = bias[col + 1];
            float2 v0 = make_float2(acc[mt][nt][0] + b0, acc[mt][nt][1] + b1);
            float2 v1 = make_float2(acc[mt][nt][2] + b0, acc[mt][nt][3] + b1);
            *(float2*)(C + (size_t)r0 * N + col) = v0;
            *(float2*)(C + (size_t)(r0 + 8) * N + col) = v1;
        }
    }
}

// ---------------- fp32 SGEMM (xW, gathered) ----------------
template <bool GATHER>
__global__ __launch_bounds__(256, 2)
void sgemm_kernel(const float* __restrict__ A, const int* __restrict__ rowidx,
                  const float* __restrict__ B, const float* __restrict__ bias,
                  float* __restrict__ C, int M, int N, int K, int lda)
{
    constexpr int BM = 128, BN = 128, BK = 8, TM = 8, TN = 8;
    __shared__ float As[BK][BM];
    __shared__ float Bs[BK][BN];

    const int brow = blockIdx.y;
    const int bcol = blockIdx.x;
    const int tid = threadIdx.x;
    const int tx = tid % 16;
    const int ty = tid / 16;

    float acc[TM][TN];
#pragma unroll
    for (int i = 0; i < TM; ++i)
#pragma unroll
        for (int j = 0; j < TN; ++j) acc[i][j] = 0.f;

    const int a_r = tid >> 1;
    const int a_k = (tid & 1) * 4;
    const int b_k = tid >> 5;
    const int b_c = (tid & 31) * 4;

    const int grow = brow * BM + a_r;
    const float* Arow;
    if (GATHER) Arow = A + (size_t)rowidx[grow] * lda;
    else        Arow = A + (size_t)grow * lda;
    const float* Bbase = B + (size_t)bcol * BN;

    float4 av = *(const float4*)(Arow + a_k);
    float4 bv = *(const float4*)(Bbase + (size_t)b_k * N + b_c);

    for (int kt = 0; kt < K; kt += BK) {
        As[a_k + 0][a_r] = av.x;
        As[a_k + 1][a_r] = av.y;
        As[a_k + 2][a_r] = av.z;
        As[a_k + 3][a_r] = av.w;
        *(float4*)(&Bs[b_k][b_c]) = bv;
        __syncthreads();
        if (kt + BK < K) {
            av = *(const float4*)(Arow + kt + BK + a_k);
            bv = *(const float4*)(Bbase + (size_t)(kt + BK + b_k) * N + b_c);
        }
#pragma unroll
        for (int k = 0; k < BK; ++k) {
            float ra[TM], rb[TN];
#pragma unroll
            for (int i = 0; i < TM; ++i) ra[i] = As[k][ty * TM + i];
#pragma unroll
            for (int j = 0; j < TN; ++j) rb[j] = Bs[k][tx * TN + j];
#pragma unroll
            for (int i = 0; i < TM; ++i)
#pragma unroll
                for (int j = 0; j < TN; ++j)
                    acc[i][j] += ra[i] * rb[j];
        }
        __syncthreads();
    }

    const int ccol0 = bcol * BN + tx * TN;
#pragma unroll
    for (int i = 0; i < TM; ++i) {
        size_t r = (size_t)(brow * BM + ty * TM + i);
        float* crow = C + r * (size_t)N + ccol0;
#pragma unroll
        for (int j = 0; j < TN; j += 4) {
            float4 v;
            v.x = acc[i][j + 0] + bias[ccol0 + j + 0];
            v.y = acc[i][j + 1] + bias[ccol0 + j + 1];
            v.z = acc[i][j + 2] + bias[ccol0 + j + 2];
            v.w = acc[i][j + 3] + bias[ccol0 + j + 3];
            *(float4*)(crow + j) = v;
        }
    }
}

// ---------------- persistent LSTM scan (bf16x3 TC, reg-resident U frags) ----------------
// 128 blocks x 256 threads (8 warps), 1/SM. Block bx owns 32 z-cols.
// U B-fragments (hi+lo) extracted ONCE into 128 registers/thread.
// h exchanged via gmem as pre-packed bf16 hi/lo pairs -> staging is a pure copy.
// Single full-k staging phase per step; warp w computes k16-steps {w, w+8, ..., w+56}.
__global__ __launch_bounds__(NTHR, 1)
void lstm_scan_kernel(const float* __restrict__ U)
{
    extern __shared__ uint32_t smw[];
    uint32_t* hhi = smw;                       // [32 m][HROW]
    uint32_t* hlo = smw + 32 * HROW;
    float*    zS  = (float*)(smw + 2 * 32 * HROW);   // [8 w][ZROW]

    const int bx = blockIdx.x;
    const int tid = threadIdx.x;
    const int w = tid >> 5;            // warp 0..7
    const int lane = tid & 31;
    const int g = lane >> 2;           // mma group row 0..7
    const int t4 = lane & 3;           // thread-in-group 0..3

    // ---- one-time: build U B-fragments in registers (via transient smem chunks)
    uint32_t uh[8][4][2], ul[8][4][2];
    {
        uint32_t* ubh = smw;                   // [32 n][UBROW] transient
        uint32_t* ubl = smw + 32 * UBROW;
        for (int ch = 0; ch < 2; ++ch) {
            __syncthreads();
            for (int i = tid; i < 2048; i += NTHR) {
                int kp = i >> 3;               // local k-pair 0..255
                int c4 = (i & 7) * 4;
                int gg = c4 >> 3, jj = c4 & 7;
                int gcol = gg * HH + bx * 8 + jj;
                int k0 = (ch * 256 + kp) * 2;
                float4 v0 = *(const float4*)(U + (size_t)k0 * G4H + gcol);
                float4 v1 = *(const float4*)(U + (size_t)(k0 + 1) * G4H + gcol);
                const float a0[4] = {v0.x, v0.y, v0.z, v0.w};
                const float a1[4] = {v1.x, v1.y, v1.z, v1.w};
#pragma unroll
                for (int q = 0; q < 4; ++q) {
                    float h0 = bfhi(a0[q]), l0 = a0[q] - h0;
                    float h1 = bfhi(a1[q]), l1 = a1[q] - h1;
                    ubh[(c4 + q) * UBROW + kp] = packbf2(h0, h1);
                    ubl[(c4 + q) * UBROW + kp] = packbf2(l0, l1);
                }
            }
            __syncthreads();
#pragma unroll
            for (int rr = 0; rr < 4; ++rr) {
                int r = ch * 4 + rr;
                int s = w + r * 8;             // global k16-step
                int kwl = s * 8 - ch * 256;    // local word base
#pragma unroll
                for (int nt = 0; nt < 4; ++nt) {
                    int ub = (nt * 8 + g) * UBROW + kwl + t4;
                    uh[r][nt][0] = ubh[ub];
                    uh[r][nt][1] = ubh[ub + 4];
                    ul[r][nt][0] = ubl[ub];
                    ul[r][nt][1] = ubl[ub + 4];
                }
            }
        }
        __syncthreads();
    }

    // ---- cell state: all 256 threads are owners; thread owns (om, oj)
    const int om = tid >> 3;           // batch row 0..31
    const int oj = tid & 7;            // local hcol 0..7
    const int ohcol = bx * 8 + oj;
    float creg = g_c[om * HH + ohcol];

    for (int t = 0; t < TT; ++t) {
        // prefetch xW for the gate phase
        float xw[4];
        {
            const float* xwp = g_xW + (size_t)(om * TT + t) * G4H + ohcol;
#pragma unroll
            for (int gg = 0; gg < 4; ++gg) xw[gg] = xwp[gg * HH];
        }

        // ---- stage full-k packed h (pure copy, 132 KB)
        {
            const uint4* srcH = (const uint4*)&g_hbf[t & 1][0][0][0];
            const uint4* srcL = (const uint4*)&g_hbf[t & 1][1][0][0];
#pragma unroll
            for (int j = 0; j < 16; ++j) {
                int idx = tid + j * NTHR;      // 0..4095
                int m = idx >> 7;
                int kp4 = idx & 127;
                *(uint4*)(hhi + m * HROW + kp4 * 4) = srcH[idx];
                *(uint4*)(hlo + m * HROW + kp4 * 4) = srcL[idx];
            }
        }
        __syncthreads();

        // ---- MMA: warp w handles k16-steps {w + r*8}
        float acc[2][4][4];
#pragma unroll
        for (int mt = 0; mt < 2; ++mt)
#pragma unroll
            for (int nt = 0; nt < 4; ++nt)
#pragma unroll
                for (int r = 0; r < 4; ++r) acc[mt][nt][r] = 0.f;

#pragma unroll
        for (int r = 0; r < 8; ++r) {
            const int kw = (w + r * 8) * 8;
            uint32_t ah[2][4], al[2][4];
#pragma unroll
            for (int mt = 0; mt < 2; ++mt) {
                int base = (mt * 16 + g) * HROW + kw + t4;
                ah[mt][0] = hhi[base];
                ah[mt][1] = hhi[base + 8 * HROW];
                ah[mt][2] = hhi[base + 4];
                ah[mt][3] = hhi[base + 8 * HROW + 4];
                al[mt][0] = hlo[base];
                al[mt][1] = hlo[base + 8 * HROW];
                al[mt][2] = hlo[base + 4];
                al[mt][3] = hlo[base + 8 * HROW + 4];
            }
#pragma unroll
            for (int mt = 0; mt < 2; ++mt)
#pragma unroll
                for (int nt = 0; nt < 4; ++nt) {
                    mma_bf16(acc[mt][nt], ah[mt][0], ah[mt][1], ah[mt][2], ah[mt][3], uh[r][nt][0], uh[r][nt][1]);
                    mma_bf16(acc[mt][nt], al[mt][0], al[mt][1], al[mt][2], al[mt][3], uh[r][nt][0], uh[r][nt][1]);
                    mma_bf16(acc[mt][nt], ah[mt][0], ah[mt][1], ah[mt][2], ah[mt][3], ul[r][nt][0], ul[r][nt][1]);
                }
        }

        // ---- store per-warp 32x32 partials (own region, no hazard)
#pragma unroll
        for (int mt = 0; mt < 2; ++mt)
#pragma unroll
            for (int nt = 0; nt < 4; ++nt) {
                int m = mt * 16 + g;
                int n = nt * 8 + t4 * 2;
                *(float2*)(zS + w * ZROW + m * 36 + n) = make_float2(acc[mt][nt][0], acc[mt][nt][1]);
                *(float2*)(zS + w * ZROW + (m + 8) * 36 + n) = make_float2(acc[mt][nt][2], acc[mt][nt][3]);
            }
        __syncthreads();

        // ---- gates: owner sums the 8 partials directly (fixed order)
        float hn;
        {
            float z[4];
#pragma unroll
            for (int gi = 0; gi < 4; ++gi) {
                float s = 0.f;
#pragma unroll
                for (int w2 = 0; w2 < 8; ++w2)
                    s += zS[w2 * ZROW + om * 36 + gi * 8 + oj];
                z[gi] = s + xw[gi];
            }
            float si = 1.f / (1.f + expf(-z[0]));
            float sf = 1.f / (1.f + expf(-z[1]));
            float tg = tanhf(z[2]);
            float so = 1.f / (1.f + expf(-z[3]));
            creg = sf * creg + si * tg;
            hn = so * tanhf(creg);
        }

        // ---- pack new h (bf16 hi/lo pairs) and publish
        {
            float hh = bfhi(hn), hl = hn - hh;
            float ph = __shfl_xor_sync(0xffffffffu, hh, 1);
            float pl = __shfl_xor_sync(0xffffffffu, hl, 1);
            if (!(oj & 1)) {
                int kp = bx * 4 + (oj >> 1);
                g_hbf[(t + 1) & 1][0][om][kp] = packbf2(hh, ph);
                g_hbf[(t + 1) & 1][1][om][kp] = packbf2(hl, pl);
            }
            g_seq[(size_t)(om * TT + t) * HH + ohcol] = to_tf32(hn);
            if (t == TT - 1) g_h[0][om * HH + ohcol] = hn;
        }

        // ---- grid barrier: per-block flags, parallel poll
        __threadfence();
        __syncthreads();
        if (tid == 0) ((volatile int*)g_flag)[bx] = t + 1;
        if (tid < NBLK) {
            while (((volatile int*)g_flag)[tid] < t + 1) { }
        }
        __syncthreads();
        __threadfence();
    }

    // ---- write back cell state
    g_c[om * HH + ohcol] = creg;
}

// ---------------- launch ----------------
extern "C" void kernel_launch(void* const* d_in, const int* in_sizes, int n_in,
                              void* d_out, int out_size)
{
    const int*   x       = (const int*)d_in[0];
    const float* state_h = (const float*)d_in[1];
    const float* state_c = (const float*)d_in[2];
    const float* emb     = (const float*)d_in[3];
    const float* W       = (const float*)d_in[4];
    const float* U       = (const float*)d_in[5];
    const float* b       = (const float*)d_in[6];
    const float* dW      = (const float*)d_in[7];
    const float* db      = (const float*)d_in[8];
    float* out = (float*)d_out;

    float* xW_ptr  = nullptr;
    float* seq_ptr = nullptr;
    float* bh_ptr  = nullptr;
    float* bl_ptr  = nullptr;
    cudaGetSymbolAddress((void**)&xW_ptr,  g_xW);
    cudaGetSymbolAddress((void**)&seq_ptr, g_seq);
    cudaGetSymbolAddress((void**)&bh_ptr,  g_Bh);
    cudaGetSymbolAddress((void**)&bl_ptr,  g_Bl);

    // unconditional (no static guards); idempotent + capture-safe
    cudaFuncSetAttribute(lstm_scan_kernel,
                         cudaFuncAttributeMaxDynamicSharedMemorySize, SCAN_SMEM_BYTES);

    // 1) load initial state (incl. packed bf16 h0) + reset flags
    init_state_kernel<<<64, 512>>>(state_h, state_c);

    // 1b) pre-split dense_W into tf32 hi/lo (pure streaming)
    split_b_kernel<<<8192, 256>>>(dW);

    // 2) xW = emb_table[x] @ W + b   (M=2048, N=4096, K=512, gathered A, fp32)
    {
        dim3 grid(G4H / 128, NROWS / 128);
        sgemm_kernel<true><<<grid, 256>>>(emb, x, W, b, xW_ptr, NROWS, G4H, EE, EE);
    }

    // 3) LSTM scan: persistent cooperative kernel (8 warps, reg-resident U frags)
    lstm_scan_kernel<<<NBLK, NTHR, SCAN_SMEM_BYTES>>>(U);

    // 4) logits = seq @ dense_W + dense_b  (tf32x2 tensor cores, pre-split B)
    {
        dim3 grid(VV / 128, NROWS / 128);
        tf32_gemm_kernel<<<grid, 256>>>(seq_ptr, bh_ptr, bl_ptr, db, out, NROWS, VV, HH);
    }

    // 5) final h, c appended after logits
    float* out_h = out + (size_t)NROWS * VV;       // 65,536,000
    float* out_c = out_h + BB * HH;                // +32,768
    write_state_kernel<<<64, 512>>>(out_h, out_c);
}

// round 12
// speedup vs baseline: 1.2118x; 1.2118x over previous
#include <cuda_runtime.h>
#include <cuda_bf16.h>
#include <math.h>
#include <stdint.h>

// Problem constants
#define VV 32000
#define EE 512
#define HH 1024
#define BB 32
#define TT 64
#define G4H (4 * HH)          // 4096
#define NROWS (BB * TT)       // 2048
#define KP 512                // packed k-pairs per row (HH/2)

#define NBLK 128              // persistent scan blocks
#define NTHR 256              // 8 warps

// scan smem word-layout
#define HROW 516
#define UBROW 260
#define ZROW 1156
#define SCAN_SMEM_WORDS (2*32*HROW + 8*ZROW)
#define SCAN_SMEM_BYTES (SCAN_SMEM_WORDS * 4)   // 169,088 B

// GEMM smem word offsets (double-buffered)
#define GA_H 0                // [2][2560]
#define GA_L 5120             // [2][2560]
#define GB_H 10240            // [2][2176]
#define GB_L 14592            // [2][2176]
#define GEMM_SMEM_WORDS 18944
#define GEMM_SMEM_BYTES (GEMM_SMEM_WORDS * 4)   // 75,776 B

// ---------------- scratch (no allocs allowed) ----------------
__device__ float    g_xW[NROWS * G4H];        // [b*T+t, 4H] input projections (+bias)
__device__ uint32_t g_sqh[(size_t)NROWS * KP];// seq packed bf16 hi pairs [row][kp]
__device__ uint32_t g_sql[(size_t)NROWS * KP];// seq packed bf16 lo pairs
__device__ float    g_h[2][BB * HH];          // final-h staging
__device__ float    g_c[BB * HH];             // cell state
__device__ int      g_flag[NBLK];             // per-block step flags
__device__ uint32_t g_hbf[2][2][32][KP];      // packed bf16 h pairs [buf][hi/lo][m][kp]
__device__ uint32_t g_Bhp[(size_t)KP * VV];   // dense_W packed bf16 hi pairs [kp][n]
__device__ uint32_t g_Blp[(size_t)KP * VV];   // dense_W packed bf16 lo pairs

// ---------------- helpers ----------------
__device__ __forceinline__ uint32_t packbf2(float a, float b) {  // a -> low half (k even)
    __nv_bfloat162 p = __floats2bfloat162_rn(a, b);
    return *reinterpret_cast<uint32_t*>(&p);
}
__device__ __forceinline__ float bfhi(float x) {
    return __bfloat162float(__float2bfloat16_rn(x));
}
__device__ __forceinline__ void mma_bf16(float* c, uint32_t a0, uint32_t a1, uint32_t a2, uint32_t a3,
                                         uint32_t b0, uint32_t b1) {
    asm volatile(
        "mma.sync.aligned.m16n8k16.row.col.f32.bf16.bf16.f32 "
        "{%0,%1,%2,%3}, {%4,%5,%6,%7}, {%8,%9}, {%0,%1,%2,%3};"
        : "+f"(c[0]), "+f"(c[1]), "+f"(c[2]), "+f"(c[3])
        : "r"(a0), "r"(a1), "r"(a2), "r"(a3), "r"(b0), "r"(b1));
}
__device__ __forceinline__ void cp16(uint32_t smem_addr, const void* gmem) {
    asm volatile("cp.async.cg.shared.global [%0], [%1], 16;" :: "r"(smem_addr), "l"(gmem) : "memory");
}
#define CP_COMMIT asm volatile("cp.async.commit_group;" ::: "memory")
#define CP_WAIT0  asm volatile("cp.async.wait_group 0;" ::: "memory")
#define CP_WAIT1  asm volatile("cp.async.wait_group 1;" ::: "memory")

// ---------------- init / finalize ----------------
__global__ void init_state_kernel(const float* __restrict__ h0, const float* __restrict__ c0) {
    int i = blockIdx.x * blockDim.x + threadIdx.x;
    if (i < BB * HH) g_c[i] = c0[i];
    if (i < BB * HH / 2) {                 // pack h0 into g_hbf[0]
        int m = i >> 9;
        int kp = i & 511;
        float a = h0[m * HH + 2 * kp];
        float b = h0[m * HH + 2 * kp + 1];
        float ah = bfhi(a), bh = bfhi(b);
        g_hbf[0][0][m][kp] = packbf2(ah, bh);
        g_hbf[0][1][m][kp] = packbf2(a - ah, b - bh);
    }
    if (i < NBLK) g_flag[i] = 0;
}

__global__ void write_state_kernel(float* __restrict__ out_h, float* __restrict__ out_c) {
    int i = blockIdx.x * blockDim.x + threadIdx.x;
    if (i < BB * HH) {
        out_h[i] = g_h[0][i];
        out_c[i] = g_c[i];
    }
}

// ---------------- dense_W -> packed bf16 hi/lo [kp][n] ----------------
__global__ void split_b_kernel(const float* __restrict__ B) {
    const size_t tot = (size_t)KP * (VV / 4);
    size_t idx = (size_t)blockIdx.x * blockDim.x + threadIdx.x;
    const size_t stride = (size_t)gridDim.x * blockDim.x;
    for (; idx < tot; idx += stride) {
        int kp = (int)(idx / (VV / 4));
        int n4 = (int)(idx % (VV / 4)) * 4;
        float4 v0 = *(const float4*)(B + (size_t)(2 * kp) * VV + n4);
        float4 v1 = *(const float4*)(B + (size_t)(2 * kp + 1) * VV + n4);
        uint4 ho, lo;
        {
            float h0 = bfhi(v0.x), h1 = bfhi(v1.x);
            ho.x = packbf2(h0, h1); lo.x = packbf2(v0.x - h0, v1.x - h1);
        }
        {
            float h0 = bfhi(v0.y), h1 = bfhi(v1.y);
            ho.y = packbf2(h0, h1); lo.y = packbf2(v0.y - h0, v1.y - h1);
        }
        {
            float h0 = bfhi(v0.z), h1 = bfhi(v1.z);
            ho.z = packbf2(h0, h1); lo.z = packbf2(v0.z - h0, v1.z - h1);
        }
        {
            float h0 = bfhi(v0.w), h1 = bfhi(v1.w);
            ho.w = packbf2(h0, h1); lo.w = packbf2(v0.w - h0, v1.w - h1);
        }
        *(uint4*)(g_Bhp + (size_t)kp * VV + n4) = ho;
        *(uint4*)(g_Blp + (size_t)kp * VV + n4) = lo;
    }
}

// ---------------- bf16x3 GEMM (logits), cp.async double-buffered ----------------
// C[M,N] = A[M,K] @ B[K,N] + bias[N]; A/B packed bf16 hi/lo pairs.
// BM=128, BN=128, BK=32 elements (16 kp). 8 warps, warp tile 64x32 (m16n8k16).
__global__ __launch_bounds__(256, 1)
void bf16_gemm_kernel(const uint32_t* __restrict__ Ahp, const uint32_t* __restrict__ Alp,
                      const uint32_t* __restrict__ Bhp, const uint32_t* __restrict__ Blp,
                      const float* __restrict__ bias, float* __restrict__ C,
                      int M, int N, int K)
{
    extern __shared__ uint32_t gsm[];
    const int tid = threadIdx.x;
    const int lane = tid & 31, wid = tid >> 5;
    const int wr = wid >> 2, wc = wid & 3;
    const int g = lane >> 2, t4 = lane & 3;
    const int bm = blockIdx.y * 128, bn = blockIdx.x * 128;
    const int kprow = K >> 1;   // 512
    const uint32_t smB = (uint32_t)__cvta_generic_to_shared(gsm);

    float acc[4][4][4];
#pragma unroll
    for (int i = 0; i < 4; ++i)
#pragma unroll
        for (int j = 0; j < 4; ++j)
#pragma unroll
            for (int r = 0; r < 4; ++r) acc[i][j][r] = 0.f;

    const int ntiles = K / 32;  // 32

    auto issue = [&](int tile, int buf) {
        int ktp = tile * 16;
#pragma unroll
        for (int i = 0; i < 2; ++i) {
            int id = tid + i * 256;
            int m = id >> 2, kp4 = id & 3;
            const uint32_t* sH = Ahp + (size_t)(bm + m) * kprow + ktp + kp4 * 4;
            const uint32_t* sL = Alp + (size_t)(bm + m) * kprow + ktp + kp4 * 4;
            cp16(smB + (GA_H + buf * 2560 + m * 20 + kp4 * 4) * 4, sH);
            cp16(smB + (GA_L + buf * 2560 + m * 20 + kp4 * 4) * 4, sL);
        }
#pragma unroll
        for (int i = 0; i < 2; ++i) {
            int id = tid + i * 256;
            int kr = id >> 5, n4 = (id & 31) * 4;
            const uint32_t* sH = Bhp + (size_t)(ktp + kr) * N + bn + n4;
            const uint32_t* sL = Blp + (size_t)(ktp + kr) * N + bn + n4;
            cp16(smB + (GB_H + buf * 2176 + kr * 136 + n4) * 4, sH);
            cp16(smB + (GB_L + buf * 2176 + kr * 136 + n4) * 4, sL);
        }
        CP_COMMIT;
    };

    issue(0, 0);
    for (int tile = 0; tile < ntiles; ++tile) {
        int buf = tile & 1;
        if (tile + 1 < ntiles) { issue(tile + 1, buf ^ 1); CP_WAIT1; }
        else                   { CP_WAIT0; }
        __syncthreads();

        const uint32_t* AhT = gsm + GA_H + buf * 2560;
        const uint32_t* AlT = gsm + GA_L + buf * 2560;
        const uint32_t* BhT = gsm + GB_H + buf * 2176;
        const uint32_t* BlT = gsm + GB_L + buf * 2176;
#pragma unroll
        for (int s = 0; s < 2; ++s) {
            const int kb = s * 8 + t4;
            uint32_t ah[4][4], al[4][4];
#pragma unroll
            for (int mt = 0; mt < 4; ++mt) {
                int r0 = wr * 64 + mt * 16 + g;
                ah[mt][0] = AhT[r0 * 20 + kb];
                ah[mt][1] = AhT[(r0 + 8) * 20 + kb];
                ah[mt][2] = AhT[r0 * 20 + kb + 4];
                ah[mt][3] = AhT[(r0 + 8) * 20 + kb + 4];
                al[mt][0] = AlT[r0 * 20 + kb];
                al[mt][1] = AlT[(r0 + 8) * 20 + kb];
                al[mt][2] = AlT[r0 * 20 + kb + 4];
                al[mt][3] = AlT[(r0 + 8) * 20 + kb + 4];
            }
#pragma unroll
            for (int nt = 0; nt < 4; ++nt) {
                int c0 = wc * 32 + nt * 8 + g;
                uint32_t bh0 = BhT[kb * 136 + c0];
                uint32_t bh1 = BhT[(kb + 4) * 136 + c0];
                uint32_t bl0 = BlT[kb * 136 + c0];
                uint32_t bl1 = BlT[(kb + 4) * 136 + c0];
#pragma unroll
                for (int mt = 0; mt < 4; ++mt) {
                    mma_bf16(acc[mt][nt], ah[mt][0], ah[mt][1], ah[mt][2], ah[mt][3], bh0, bh1);
                    mma_bf16(acc[mt][nt], al[mt][0], al[mt][1], al[mt][2], al[mt][3], bh0, bh1);
                    mma_bf16(acc[mt][nt], ah[mt][0], ah[mt][1], ah[mt][2], ah[mt][3], bl0, bl1);
                }
            }
        }
        __syncthreads();
    }

    // epilogue (m16n8 C layout: rows g, g+8; cols 2*t4, 2*t4+1)
#pragma unroll
    for (int mt = 0; mt < 4; ++mt) {
        int r0 = bm + wr * 64 + mt * 16 + g;
#pragma unroll
        for (int nt = 0; nt < 4; ++nt) {
            int col = bn + wc * 32 + nt * 8 + 2 * t4;
            float b0 = bias[col], b1 = bias[col + 1];
            float2 v0 = make_float2(acc[mt][nt][0] + b0, acc[mt][nt][1] + b1);
            float2 v1 = make_float2(acc[mt][nt][2] + b0, acc[mt][nt][3] + b1);
            *(float2*)(C + (size_t)r0 * N + col) = v0;
            *(float2*)(C + (size_t)(r0 + 8) * N + col) = v1;
        }
    }
}

// ---------------- fp32 SGEMM (xW, gathered) ----------------
template <bool GATHER>
__global__ __launch_bounds__(256, 2)
void sgemm_kernel(const float* __restrict__ A, const int* __restrict__ rowidx,
                  const float* __restrict__ B, const float* __restrict__ bias,
                  float* __restrict__ C, int M, int N, int K, int lda)
{
    constexpr int BM = 128, BN = 128, BK = 8, TM = 8, TN = 8;
    __shared__ float As[BK][BM];
    __shared__ float Bs[BK][BN];

    const int brow = blockIdx.y;
    const int bcol = blockIdx.x;
    const int tid = threadIdx.x;
    const int tx = tid % 16;
    const int ty = tid / 16;

    float acc[TM][TN];
#pragma unroll
    for (int i = 0; i < TM; ++i)
#pragma unroll
        for (int j = 0; j < TN; ++j) acc[i][j] = 0.f;

    const int a_r = tid >> 1;
    const int a_k = (tid & 1) * 4;
    const int b_k = tid >> 5;
    const int b_c = (tid & 31) * 4;

    const int grow = brow * BM + a_r;
    const float* Arow;
    if (GATHER) Arow = A + (size_t)rowidx[grow] * lda;
    else        Arow = A + (size_t)grow * lda;
    const float* Bbase = B + (size_t)bcol * BN;

    float4 av = *(const float4*)(Arow + a_k);
    float4 bv = *(const float4*)(Bbase + (size_t)b_k * N + b_c);

    for (int kt = 0; kt < K; kt += BK) {
        As[a_k + 0][a_r] = av.x;
        As[a_k + 1][a_r] = av.y;
        As[a_k + 2][a_r] = av.z;
        As[a_k + 3][a_r] = av.w;
        *(float4*)(&Bs[b_k][b_c]) = bv;
        __syncthreads();
        if (kt + BK < K) {
            av = *(const float4*)(Arow + kt + BK + a_k);
            bv = *(const float4*)(Bbase + (size_t)(kt + BK + b_k) * N + b_c);
        }
#pragma unroll
        for (int k = 0; k < BK; ++k) {
            float ra[TM], rb[TN];
#pragma unroll
            for (int i = 0; i < TM; ++i) ra[i] = As[k][ty * TM + i];
#pragma unroll
            for (int j = 0; j < TN; ++j) rb[j] = Bs[k][tx * TN + j];
#pragma unroll
            for (int i = 0; i < TM; ++i)
#pragma unroll
                for (int j = 0; j < TN; ++j)
                    acc[i][j] += ra[i] * rb[j];
        }
        __syncthreads();
    }

    const int ccol0 = bcol * BN + tx * TN;
#pragma unroll
    for (int i = 0; i < TM; ++i) {
        size_t r = (size_t)(brow * BM + ty * TM + i);
        float* crow = C + r * (size_t)N + ccol0;
#pragma unroll
        for (int j = 0; j < TN; j += 4) {
            float4 v;
            v.x = acc[i][j + 0] + bias[ccol0 + j + 0];
            v.y = acc[i][j + 1] + bias[ccol0 + j + 1];
            v.z = acc[i][j + 2] + bias[ccol0 + j + 2];
            v.w = acc[i][j + 3] + bias[ccol0 + j + 3];
            *(float4*)(crow + j) = v;
        }
    }
}

// ---------------- persistent LSTM scan (bf16x3 TC, cp.async staging) ----------------
// 128 blocks x 256 threads, 1/SM. Block bx owns 32 z-cols (8 hcols x 4 gates).
// U B-fragments in registers (built once). h exchanged via gmem as pre-packed
// bf16 hi/lo pairs; staging is cp.async (no register pressure).
__global__ __launch_bounds__(NTHR, 1)
void lstm_scan_kernel(const float* __restrict__ U)
{
    extern __shared__ uint32_t smw[];
    uint32_t* hhi = smw;                       // [32 m][HROW]
    uint32_t* hlo = smw + 32 * HROW;
    float*    zS  = (float*)(smw + 2 * 32 * HROW);   // [8 w][ZROW]

    const int bx = blockIdx.x;
    const int tid = threadIdx.x;
    const int w = tid >> 5;
    const int lane = tid & 31;
    const int g = lane >> 2;
    const int t4 = lane & 3;

    const uint32_t hhiB = (uint32_t)__cvta_generic_to_shared(hhi);
    const uint32_t hloB = (uint32_t)__cvta_generic_to_shared(hlo);

    // ---- one-time: build U B-fragments in registers (via transient smem chunks)
    uint32_t uh[8][4][2], ul[8][4][2];
    {
        uint32_t* ubh = smw;
        uint32_t* ubl = smw + 32 * UBROW;
        for (int ch = 0; ch < 2; ++ch) {
            __syncthreads();
            for (int i = tid; i < 2048; i += NTHR) {
                int kp = i >> 3;
                int c4 = (i & 7) * 4;
                int gg = c4 >> 3, jj = c4 & 7;
                int gcol = gg * HH + bx * 8 + jj;
                int k0 = (ch * 256 + kp) * 2;
                float4 v0 = *(const float4*)(U + (size_t)k0 * G4H + gcol);
                float4 v1 = *(const float4*)(U + (size_t)(k0 + 1) * G4H + gcol);
                const float a0[4] = {v0.x, v0.y, v0.z, v0.w};
                const float a1[4] = {v1.x, v1.y, v1.z, v1.w};
#pragma unroll
                for (int q = 0; q < 4; ++q) {
                    float h0 = bfhi(a0[q]), l0 = a0[q] - h0;
                    float h1 = bfhi(a1[q]), l1 = a1[q] - h1;
                    ubh[(c4 + q) * UBROW + kp] = packbf2(h0, h1);
                    ubl[(c4 + q) * UBROW + kp] = packbf2(l0, l1);
                }
            }
            __syncthreads();
#pragma unroll
            for (int rr = 0; rr < 4; ++rr) {
                int r = ch * 4 + rr;
                int s = w + r * 8;
                int kwl = s * 8 - ch * 256;
#pragma unroll
                for (int nt = 0; nt < 4; ++nt) {
                    int ub = (nt * 8 + g) * UBROW + kwl + t4;
                    uh[r][nt][0] = ubh[ub];
                    uh[r][nt][1] = ubh[ub + 4];
                    ul[r][nt][0] = ubl[ub];
                    ul[r][nt][1] = ubl[ub + 4];
                }
            }
        }
        __syncthreads();
    }

    // ---- cell state: thread owns (om, oj)
    const int om = tid >> 3;
    const int oj = tid & 7;
    const int ohcol = bx * 8 + oj;
    float creg = g_c[om * HH + ohcol];

    for (int t = 0; t < TT; ++t) {
        // prefetch xW for the gate phase
        float xw[4];
        {
            const float* xwp = g_xW + (size_t)(om * TT + t) * G4H + ohcol;
#pragma unroll
            for (int gg = 0; gg < 4; ++gg) xw[gg] = xwp[gg * HH];
        }

        // ---- stage full-k packed h via cp.async (132 KB, no register pressure)
        {
            const uint4* srcH = (const uint4*)&g_hbf[t & 1][0][0][0];
            const uint4* srcL = (const uint4*)&g_hbf[t & 1][1][0][0];
#pragma unroll
            for (int j = 0; j < 16; ++j) {
                int idx = tid + j * NTHR;      // 0..4095
                int m = idx >> 7;
                int kp4 = idx & 127;
                uint32_t off = (m * HROW + kp4 * 4) * 4;
                cp16(hhiB + off, srcH + idx);
                cp16(hloB + off, srcL + idx);
            }
            CP_COMMIT;
            CP_WAIT0;
        }
        __syncthreads();

        // ---- MMA: warp w handles k16-steps {w + r*8}
        float acc[2][4][4];
#pragma unroll
        for (int mt = 0; mt < 2; ++mt)
#pragma unroll
            for (int nt = 0; nt < 4; ++nt)
#pragma unroll
                for (int r = 0; r < 4; ++r) acc[mt][nt][r] = 0.f;

#pragma unroll
        for (int r = 0; r < 8; ++r) {
            const int kw = (w + r * 8) * 8;
            uint32_t ah[2][4], al[2][4];
#pragma unroll
            for (int mt = 0; mt < 2; ++mt) {
                int base = (mt * 16 + g) * HROW + kw + t4;
                ah[mt][0] = hhi[base];
                ah[mt][1] = hhi[base + 8 * HROW];
                ah[mt][2] = hhi[base + 4];
                ah[mt][3] = hhi[base + 8 * HROW + 4];
                al[mt][0] = hlo[base];
                al[mt][1] = hlo[base + 8 * HROW];
                al[mt][2] = hlo[base + 4];
                al[mt][3] = hlo[base + 8 * HROW + 4];
            }
#pragma unroll
            for (int mt = 0; mt < 2; ++mt)
#pragma unroll
                for (int nt = 0; nt < 4; ++nt) {
                    mma_bf16(acc[mt][nt], ah[mt][0], ah[mt][1], ah[mt][2], ah[mt][3], uh[r][nt][0], uh[r][nt][1]);
                    mma_bf16(acc[mt][nt], al[mt][0], al[mt][1], al[mt][2], al[mt][3], uh[r][nt][0], uh[r][nt][1]);
                    mma_bf16(acc[mt][nt], ah[mt][0], ah[mt][1], ah[mt][2], ah[mt][3], ul[r][nt][0], ul[r][nt][1]);
                }
        }

        // ---- store per-warp 32x32 partials
#pragma unroll
        for (int mt = 0; mt < 2; ++mt)
#pragma unroll
            for (int nt = 0; nt < 4; ++nt) {
                int m = mt * 16 + g;
                int n = nt * 8 + t4 * 2;
                *(float2*)(zS + w * ZROW + m * 36 + n) = make_float2(acc[mt][nt][0], acc[mt][nt][1]);
                *(float2*)(zS + w * ZROW + (m + 8) * 36 + n) = make_float2(acc[mt][nt][2], acc[mt][nt][3]);
            }
        __syncthreads();

        // ---- gates: owner sums the 8 partials (fixed order)
        float hn;
        {
            float z[4];
#pragma unroll
            for (int gi = 0; gi < 4; ++gi) {
                float s = 0.f;
#pragma unroll
                for (int w2 = 0; w2 < 8; ++w2)
                    s += zS[w2 * ZROW + om * 36 + gi * 8 + oj];
                z[gi] = s + xw[gi];
            }
            float si = 1.f / (1.f + expf(-z[0]));
            float sf = 1.f / (1.f + expf(-z[1]));
            float tg = tanhf(z[2]);
            float so = 1.f / (1.f + expf(-z[3]));
            creg = sf * creg + si * tg;
            hn = so * tanhf(creg);
        }

        // ---- pack new h (bf16 hi/lo pairs); publish h-exchange + seq
        {
            float hh = bfhi(hn), hl = hn - hh;
            float ph = __shfl_xor_sync(0xffffffffu, hh, 1);
            float pl = __shfl_xor_sync(0xffffffffu, hl, 1);
            if (!(oj & 1)) {
                int kp = bx * 4 + (oj >> 1);
                uint32_t wh = packbf2(hh, ph);
                uint32_t wl = packbf2(hl, pl);
                g_hbf[(t + 1) & 1][0][om][kp] = wh;
                g_hbf[(t + 1) & 1][1][om][kp] = wl;
                size_t row = (size_t)om * TT + t;
                g_sqh[row * KP + kp] = wh;
                g_sql[row * KP + kp] = wl;
            }
            if (t == TT - 1) g_h[0][om * HH + ohcol] = hn;
        }

        // ---- grid barrier: per-block flags, parallel poll
        __threadfence();
        __syncthreads();
        if (tid == 0) ((volatile int*)g_flag)[bx] = t + 1;
        if (tid < NBLK) {
            while (((volatile int*)g_flag)[tid] < t + 1) { }
        }
        __syncthreads();
        __threadfence();
    }

    // ---- write back cell state
    g_c[om * HH + ohcol] = creg;
}

// ---------------- launch ----------------
extern "C" void kernel_launch(void* const* d_in, const int* in_sizes, int n_in,
                              void* d_out, int out_size)
{
    const int*   x       = (const int*)d_in[0];
    const float* state_h = (const float*)d_in[1];
    const float* state_c = (const float*)d_in[2];
    const float* emb     = (const float*)d_in[3];
    const float* W       = (const float*)d_in[4];
    const float* U       = (const float*)d_in[5];
    const float* b       = (const float*)d_in[6];
    const float* dW      = (const float*)d_in[7];
    const float* db      = (const float*)d_in[8];
    float* out = (float*)d_out;

    float*    xW_ptr  = nullptr;
    uint32_t* sqh_ptr = nullptr;
    uint32_t* sql_ptr = nullptr;
    uint32_t* bhp_ptr = nullptr;
    uint32_t* blp_ptr = nullptr;
    cudaGetSymbolAddress((void**)&xW_ptr,  g_xW);
    cudaGetSymbolAddress((void**)&sqh_ptr, g_sqh);
    cudaGetSymbolAddress((void**)&sql_ptr, g_sql);
    cudaGetSymbolAddress((void**)&bhp_ptr, g_Bhp);
    cudaGetSymbolAddress((void**)&blp_ptr, g_Blp);

    // unconditional (no static guards); idempotent + capture-safe
    cudaFuncSetAttribute(lstm_scan_kernel,
                         cudaFuncAttributeMaxDynamicSharedMemorySize, SCAN_SMEM_BYTES);
    cudaFuncSetAttribute(bf16_gemm_kernel,
                         cudaFuncAttributeMaxDynamicSharedMemorySize, GEMM_SMEM_BYTES);

    // 1) load initial state (incl. packed bf16 h0) + reset flags
    init_state_kernel<<<64, 512>>>(state_h, state_c);

    // 1b) pre-split dense_W into packed bf16 hi/lo (pure streaming)
    split_b_kernel<<<8192, 256>>>(dW);

    // 2) xW = emb_table[x] @ W + b   (M=2048, N=4096, K=512, gathered A, fp32)
    {
        dim3 grid(G4H / 128, NROWS / 128);
        sgemm_kernel<true><<<grid, 256>>>(emb, x, W, b, xW_ptr, NROWS, G4H, EE, EE);
    }

    // 3) LSTM scan: persistent cooperative kernel (bf16x3, cp.async staging)
    lstm_scan_kernel<<<NBLK, NTHR, SCAN_SMEM_BYTES>>>(U);

    // 4) logits = seq @ dense_W + dense_b  (bf16x3 tensor cores, double-buffered)
    {
        dim3 grid(VV / 128, NROWS / 128);
        bf16_gemm_kernel<<<grid, 256, GEMM_SMEM_BYTES>>>(
            sqh_ptr, sql_ptr, bhp_ptr, blp_ptr, db, out, NROWS, VV, HH);
    }

    // 5) final h, c appended after logits
    float* out_h = out + (size_t)NROWS * VV;       // 65,536,000
    float* out_c = out_h + BB * HH;                // +32,768
    write_state_kernel<<<64, 512>>>(out_h, out_c);
}

// round 13
// speedup vs baseline: 1.3746x; 1.1344x over previous
#include <cuda_runtime.h>
#include <cuda_bf16.h>
#include <math.h>
#include <stdint.h>

// Problem constants
#define VV 32000
#define EE 512
#define HH 1024
#define BB 32
#define TT 64
#define G4H (4 * HH)          // 4096
#define NROWS (BB * TT)       // 2048
#define KP 512                // packed k-pairs per row (HH/2)

#define NBLK 128              // persistent scan blocks
#define NTHR 256              // 8 warps

// scan smem (words): U-build transient (2*32*260) unions with zS (8*1156)
#define UBROW 260
#define ZROW 1156
#define SCAN_SMEM_WORDS (2*32*UBROW)
#define SCAN_SMEM_BYTES (SCAN_SMEM_WORDS * 4)   // 66,560 B

// GEMM smem word offsets (double-buffered)
#define GA_H 0                // [2][2560]
#define GA_L 5120             // [2][2560]
#define GB_H 10240            // [2][2176]
#define GB_L 14592            // [2][2176]
#define GEMM_SMEM_WORDS 18944
#define GEMM_SMEM_BYTES (GEMM_SMEM_WORDS * 4)   // 75,776 B

// ---------------- scratch (no allocs allowed) ----------------
__device__ float    g_xW[NROWS * G4H];        // [b*T+t, 4H] input projections (+bias)
__device__ uint32_t g_sqh[(size_t)NROWS * KP];// seq packed bf16 hi pairs [row][kp]
__device__ uint32_t g_sql[(size_t)NROWS * KP];// seq packed bf16 lo pairs
__device__ float    g_h[2][BB * HH];          // final-h staging
__device__ float    g_c[BB * HH];             // cell state
__device__ int      g_flag[NBLK];             // per-block publish counters
__device__ uint32_t g_hbf[2][2][32][KP];      // packed bf16 h pairs [buf][hi/lo][m][kp]
__device__ uint32_t g_Bhp[(size_t)KP * VV];   // dense_W packed bf16 hi pairs [kp][n]
__device__ uint32_t g_Blp[(size_t)KP * VV];   // dense_W packed bf16 lo pairs

// ---------------- helpers ----------------
__device__ __forceinline__ uint32_t packbf2(float a, float b) {  // a -> low half (k even)
    __nv_bfloat162 p = __floats2bfloat162_rn(a, b);
    return *reinterpret_cast<uint32_t*>(&p);
}
__device__ __forceinline__ float bfhi(float x) {
    return __bfloat162float(__float2bfloat16_rn(x));
}
__device__ __forceinline__ void mma_bf16(float* c, uint32_t a0, uint32_t a1, uint32_t a2, uint32_t a3,
                                         uint32_t b0, uint32_t b1) {
    asm volatile(
        "mma.sync.aligned.m16n8k16.row.col.f32.bf16.bf16.f32 "
        "{%0,%1,%2,%3}, {%4,%5,%6,%7}, {%8,%9}, {%0,%1,%2,%3};"
        : "+f"(c[0]), "+f"(c[1]), "+f"(c[2]), "+f"(c[3])
        : "r"(a0), "r"(a1), "r"(a2), "r"(a3), "r"(b0), "r"(b1));
}
__device__ __forceinline__ void cp16(uint32_t smem_addr, const void* gmem) {
    asm volatile("cp.async.cg.shared.global [%0], [%1], 16;" :: "r"(smem_addr), "l"(gmem) : "memory");
}
#define CP_COMMIT asm volatile("cp.async.commit_group;" ::: "memory")
#define CP_WAIT0  asm volatile("cp.async.wait_group 0;" ::: "memory")
#define CP_WAIT1  asm volatile("cp.async.wait_group 1;" ::: "memory")

// ---------------- init / finalize ----------------
__global__ void init_state_kernel(const float* __restrict__ h0, const float* __restrict__ c0) {
    int i = blockIdx.x * blockDim.x + threadIdx.x;
    if (i < BB * HH) g_c[i] = c0[i];
    if (i < BB * HH / 2) {                 // pack h0 into g_hbf[0]
        int m = i >> 9;
        int kp = i & 511;
        float a = h0[m * HH + 2 * kp];
        float b = h0[m * HH + 2 * kp + 1];
        float ah = bfhi(a), bh = bfhi(b);
        g_hbf[0][0][m][kp] = packbf2(ah, bh);
        g_hbf[0][1][m][kp] = packbf2(a - ah, b - bh);
    }
    if (i < NBLK) g_flag[i] = 0;
}

__global__ void write_state_kernel(float* __restrict__ out_h, float* __restrict__ out_c) {
    int i = blockIdx.x * blockDim.x + threadIdx.x;
    if (i < BB * HH) {
        out_h[i] = g_h[0][i];
        out_c[i] = g_c[i];
    }
}

// ---------------- dense_W -> packed bf16 hi/lo [kp][n] ----------------
__global__ void split_b_kernel(const float* __restrict__ B) {
    const size_t tot = (size_t)KP * (VV / 4);
    size_t idx = (size_t)blockIdx.x * blockDim.x + threadIdx.x;
    const size_t stride = (size_t)gridDim.x * blockDim.x;
    for (; idx < tot; idx += stride) {
        int kp = (int)(idx / (VV / 4));
        int n4 = (int)(idx % (VV / 4)) * 4;
        float4 v0 = *(const float4*)(B + (size_t)(2 * kp) * VV + n4);
        float4 v1 = *(const float4*)(B + (size_t)(2 * kp + 1) * VV + n4);
        uint4 ho, lo;
        {
            float h0 = bfhi(v0.x), h1 = bfhi(v1.x);
            ho.x = packbf2(h0, h1); lo.x = packbf2(v0.x - h0, v1.x - h1);
        }
        {
            float h0 = bfhi(v0.y), h1 = bfhi(v1.y);
            ho.y = packbf2(h0, h1); lo.y = packbf2(v0.y - h0, v1.y - h1);
        }
        {
            float h0 = bfhi(v0.z), h1 = bfhi(v1.z);
            ho.z = packbf2(h0, h1); lo.z = packbf2(v0.z - h0, v1.z - h1);
        }
        {
            float h0 = bfhi(v0.w), h1 = bfhi(v1.w);
            ho.w = packbf2(h0, h1); lo.w = packbf2(v0.w - h0, v1.w - h1);
        }
        *(uint4*)(g_Bhp + (size_t)kp * VV + n4) = ho;
        *(uint4*)(g_Blp + (size_t)kp * VV + n4) = lo;
    }
}

// ---------------- bf16x3 GEMM (logits), cp.async double-buffered ----------------
__global__ __launch_bounds__(256, 1)
void bf16_gemm_kernel(const uint32_t* __restrict__ Ahp, const uint32_t* __restrict__ Alp,
                      const uint32_t* __restrict__ Bhp, const uint32_t* __restrict__ Blp,
                      const float* __restrict__ bias, float* __restrict__ C,
                      int M, int N, int K)
{
    extern __shared__ uint32_t gsm[];
    const int tid = threadIdx.x;
    const int lane = tid & 31, wid = tid >> 5;
    const int wr = wid >> 2, wc = wid & 3;
    const int g = lane >> 2, t4 = lane & 3;
    const int bm = blockIdx.y * 128, bn = blockIdx.x * 128;
    const int kprow = K >> 1;   // 512
    const uint32_t smB = (uint32_t)__cvta_generic_to_shared(gsm);

    float acc[4][4][4];
#pragma unroll
    for (int i = 0; i < 4; ++i)
#pragma unroll
        for (int j = 0; j < 4; ++j)
#pragma unroll
            for (int r = 0; r < 4; ++r) acc[i][j][r] = 0.f;

    const int ntiles = K / 32;  // 32

    auto issue = [&](int tile, int buf) {
        int ktp = tile * 16;
#pragma unroll
        for (int i = 0; i < 2; ++i) {
            int id = tid + i * 256;
            int m = id >> 2, kp4 = id & 3;
            const uint32_t* sH = Ahp + (size_t)(bm + m) * kprow + ktp + kp4 * 4;
            const uint32_t* sL = Alp + (size_t)(bm + m) * kprow + ktp + kp4 * 4;
            cp16(smB + (GA_H + buf * 2560 + m * 20 + kp4 * 4) * 4, sH);
            cp16(smB + (GA_L + buf * 2560 + m * 20 + kp4 * 4) * 4, sL);
        }
#pragma unroll
        for (int i = 0; i < 2; ++i) {
            int id = tid + i * 256;
            int kr = id >> 5, n4 = (id & 31) * 4;
            const uint32_t* sH = Bhp + (size_t)(ktp + kr) * N + bn + n4;
            const uint32_t* sL = Blp + (size_t)(ktp + kr) * N + bn + n4;
            cp16(smB + (GB_H + buf * 2176 + kr * 136 + n4) * 4, sH);
            cp16(smB + (GB_L + buf * 2176 + kr * 136 + n4) * 4, sL);
        }
        CP_COMMIT;
    };

    issue(0, 0);
    for (int tile = 0; tile < ntiles; ++tile) {
        int buf = tile & 1;
        if (tile + 1 < ntiles) { issue(tile + 1, buf ^ 1); CP_WAIT1; }
        else                   { CP_WAIT0; }
        __syncthreads();

        const uint32_t* AhT = gsm + GA_H + buf * 2560;
        const uint32_t* AlT = gsm + GA_L + buf * 2560;
        const uint32_t* BhT = gsm + GB_H + buf * 2176;
        const uint32_t* BlT = gsm + GB_L + buf * 2176;
#pragma unroll
        for (int s = 0; s < 2; ++s) {
            const int kb = s * 8 + t4;
            uint32_t ah[4][4], al[4][4];
#pragma unroll
            for (int mt = 0; mt < 4; ++mt) {
                int r0 = wr * 64 + mt * 16 + g;
                ah[mt][0] = AhT[r0 * 20 + kb];
                ah[mt][1] = AhT[(r0 + 8) * 20 + kb];
                ah[mt][2] = AhT[r0 * 20 + kb + 4];
                ah[mt][3] = AhT[(r0 + 8) * 20 + kb + 4];
                al[mt][0] = AlT[r0 * 20 + kb];
                al[mt][1] = AlT[(r0 + 8) * 20 + kb];
                al[mt][2] = AlT[r0 * 20 + kb + 4];
                al[mt][3] = AlT[(r0 + 8) * 20 + kb + 4];
            }
#pragma unroll
            for (int nt = 0; nt < 4; ++nt) {
                int c0 = wc * 32 + nt * 8 + g;
                uint32_t bh0 = BhT[kb * 136 + c0];
                uint32_t bh1 = BhT[(kb + 4) * 136 + c0];
                uint32_t bl0 = BlT[kb * 136 + c0];
                uint32_t bl1 = BlT[(kb + 4) * 136 + c0];
#pragma unroll
                for (int mt = 0; mt < 4; ++mt) {
                    mma_bf16(acc[mt][nt], ah[mt][0], ah[mt][1], ah[mt][2], ah[mt][3], bh0, bh1);
                    mma_bf16(acc[mt][nt], al[mt][0], al[mt][1], al[mt][2], al[mt][3], bh0, bh1);
                    mma_bf16(acc[mt][nt], ah[mt][0], ah[mt][1], ah[mt][2], ah[mt][3], bl0, bl1);
                }
            }
        }
        __syncthreads();
    }

#pragma unroll
    for (int mt = 0; mt < 4; ++mt) {
        int r0 = bm + wr * 64 + mt * 16 + g;
#pragma unroll
        for (int nt = 0; nt < 4; ++nt) {
            int col = bn + wc * 32 + nt * 8 + 2 * t4;
            float b0 = bias[col], b1 = bias[col + 1];
            float2 v0 = make_float2(acc[mt][nt][0] + b0, acc[mt][nt][1] + b1);
            float2 v1 = make_float2(acc[mt][nt][2] + b0, acc[mt][nt][3] + b1);
            *(float2*)(C + (size_t)r0 * N + col) = v0;
            *(float2*)(C + (size_t)(r0 + 8) * N + col) = v1;
        }
    }
}

// ---------------- fp32 SGEMM (xW, gathered) ----------------
template <bool GATHER>
__global__ __launch_bounds__(256, 2)
void sgemm_kernel(const float* __restrict__ A, const int* __restrict__ rowidx,
                  const float* __restrict__ B, const float* __restrict__ bias,
                  float* __restrict__ C, int M, int N, int K, int lda)
{
    constexpr int BM = 128, BN = 128, BK = 8, TM = 8, TN = 8;
    __shared__ float As[BK][BM];
    __shared__ float Bs[BK][BN];

    const int brow = blockIdx.y;
    const int bcol = blockIdx.x;
    const int tid = threadIdx.x;
    const int tx = tid % 16;
    const int ty = tid / 16;

    float acc[TM][TN];
#pragma unroll
    for (int i = 0; i < TM; ++i)
#pragma unroll
        for (int j = 0; j < TN; ++j) acc[i][j] = 0.f;

    const int a_r = tid >> 1;
    const int a_k = (tid & 1) * 4;
    const int b_k = tid >> 5;
    const int b_c = (tid & 31) * 4;

    const int grow = brow * BM + a_r;
    const float* Arow;
    if (GATHER) Arow = A + (size_t)rowidx[grow] * lda;
    else        Arow = A + (size_t)grow * lda;
    const float* Bbase = B + (size_t)bcol * BN;

    float4 av = *(const float4*)(Arow + a_k);
    float4 bv = *(const float4*)(Bbase + (size_t)b_k * N + b_c);

    for (int kt = 0; kt < K; kt += BK) {
        As[a_k + 0][a_r] = av.x;
        As[a_k + 1][a_r] = av.y;
        As[a_k + 2][a_r] = av.z;
        As[a_k + 3][a_r] = av.w;
        *(float4*)(&Bs[b_k][b_c]) = bv;
        __syncthreads();
        if (kt + BK < K) {
            av = *(const float4*)(Arow + kt + BK + a_k);
            bv = *(const float4*)(Bbase + (size_t)(kt + BK + b_k) * N + b_c);
        }
#pragma unroll
        for (int k = 0; k < BK; ++k) {
            float ra[TM], rb[TN];
#pragma unroll
            for (int i = 0; i < TM; ++i) ra[i] = As[k][ty * TM + i];
#pragma unroll
            for (int j = 0; j < TN; ++j) rb[j] = Bs[k][tx * TN + j];
#pragma unroll
            for (int i = 0; i < TM; ++i)
#pragma unroll
                for (int j = 0; j < TN; ++j)
                    acc[i][j] += ra[i] * rb[j];
        }
        __syncthreads();
    }

    const int ccol0 = bcol * BN + tx * TN;
#pragma unroll
    for (int i = 0; i < TM; ++i) {
        size_t r = (size_t)(brow * BM + ty * TM + i);
        float* crow = C + r * (size_t)N + ccol0;
#pragma unroll
        for (int j = 0; j < TN; j += 4) {
            float4 v;
            v.x = acc[i][j + 0] + bias[ccol0 + j + 0];
            v.y = acc[i][j + 1] + bias[ccol0 + j + 1];
            v.z = acc[i][j + 2] + bias[ccol0 + j + 2];
            v.w = acc[i][j + 3] + bias[ccol0 + j + 3];
            *(float4*)(crow + j) = v;
        }
    }
}

// ---------------- persistent LSTM scan (bf16x3 TC, dataflow sync) ----------------
// 128 blocks x 256 threads. Block bx owns 32 z-cols (8 hcols x 4 gates).
// U B-fragments in registers (built once). NO smem h staging, NO full barrier:
// warps LDG A-fragments straight from g_hbf (layout matches fragment words) and
// wait only on the 2 producer blocks of each k16-slice (fixed order -> deterministic).
// 2-buffer ping-pong is overwrite-safe: publishing step t+2 requires having
// observed ALL flags >= t+2, which implies every block finished reading buf (t+1)&1.
__global__ __launch_bounds__(NTHR, 1)
void lstm_scan_kernel(const float* __restrict__ U)
{
    extern __shared__ uint32_t smw[];
    float* zS = (float*)smw;           // [8 w][ZROW] (after U-build phase)

    const int bx = blockIdx.x;
    const int tid = threadIdx.x;
    const int w = tid >> 5;
    const int lane = tid & 31;
    const int g = lane >> 2;
    const int t4 = lane & 3;

    // ---- one-time: build U B-fragments in registers (transient smem chunks)
    uint32_t uh[8][4][2], ul[8][4][2];
    {
        uint32_t* ubh = smw;
        uint32_t* ubl = smw + 32 * UBROW;
        for (int ch = 0; ch < 2; ++ch) {
            __syncthreads();
            for (int i = tid; i < 2048; i += NTHR) {
                int kp = i >> 3;
                int c4 = (i & 7) * 4;
                int gg = c4 >> 3, jj = c4 & 7;
                int gcol = gg * HH + bx * 8 + jj;
                int k0 = (ch * 256 + kp) * 2;
                float4 v0 = *(const float4*)(U + (size_t)k0 * G4H + gcol);
                float4 v1 = *(const float4*)(U + (size_t)(k0 + 1) * G4H + gcol);
                const float a0[4] = {v0.x, v0.y, v0.z, v0.w};
                const float a1[4] = {v1.x, v1.y, v1.z, v1.w};
#pragma unroll
                for (int q = 0; q < 4; ++q) {
                    float h0 = bfhi(a0[q]), l0 = a0[q] - h0;
                    float h1 = bfhi(a1[q]), l1 = a1[q] - h1;
                    ubh[(c4 + q) * UBROW + kp] = packbf2(h0, h1);
                    ubl[(c4 + q) * UBROW + kp] = packbf2(l0, l1);
                }
            }
            __syncthreads();
#pragma unroll
            for (int rr = 0; rr < 4; ++rr) {
                int r = ch * 4 + rr;
                int s = w + r * 8;
                int kwl = s * 8 - ch * 256;
#pragma unroll
                for (int nt = 0; nt < 4; ++nt) {
                    int ub = (nt * 8 + g) * UBROW + kwl + t4;
                    uh[r][nt][0] = ubh[ub];
                    uh[r][nt][1] = ubh[ub + 4];
                    ul[r][nt][0] = ubl[ub];
                    ul[r][nt][1] = ubl[ub + 4];
                }
            }
        }
        __syncthreads();
    }

    // ---- cell state: thread owns (om, oj)
    const int om = tid >> 3;
    const int oj = tid & 7;
    const int ohcol = bx * 8 + oj;
    float creg = g_c[om * HH + ohcol];

    volatile int* flags = (volatile int*)g_flag;

    for (int t = 0; t < TT; ++t) {
        // prefetch xW for the gate phase
        float xw[4];
        {
            const float* xwp = g_xW + (size_t)(om * TT + t) * G4H + ohcol;
#pragma unroll
            for (int gg = 0; gg < 4; ++gg) xw[gg] = xwp[gg * HH];
        }

        const uint32_t* Hsrc = &g_hbf[t & 1][0][0][0];
        const uint32_t* Lsrc = &g_hbf[t & 1][1][0][0];

        float acc[2][4][4];
#pragma unroll
        for (int mt = 0; mt < 2; ++mt)
#pragma unroll
            for (int nt = 0; nt < 4; ++nt)
#pragma unroll
                for (int r = 0; r < 4; ++r) acc[mt][nt][r] = 0.f;

        // ---- dataflow MMA: slice s = w + r*8 needs producers 2s, 2s+1
#pragma unroll
        for (int r = 0; r < 8; ++r) {
            const int s = w + r * 8;
            if (lane < 2) {
                while (flags[2 * s + lane] < t) { }
            }
            __syncwarp();

            uint32_t ah[2][4], al[2][4];
#pragma unroll
            for (int mt = 0; mt < 2; ++mt) {
                int base = (mt * 16 + g) * KP + s * 8 + t4;
                ah[mt][0] = Hsrc[base];
                ah[mt][1] = Hsrc[base + 8 * KP];
                ah[mt][2] = Hsrc[base + 4];
                ah[mt][3] = Hsrc[base + 8 * KP + 4];
                al[mt][0] = Lsrc[base];
                al[mt][1] = Lsrc[base + 8 * KP];
                al[mt][2] = Lsrc[base + 4];
                al[mt][3] = Lsrc[base + 8 * KP + 4];
            }
#pragma unroll
            for (int mt = 0; mt < 2; ++mt)
#pragma unroll
                for (int nt = 0; nt < 4; ++nt) {
                    mma_bf16(acc[mt][nt], ah[mt][0], ah[mt][1], ah[mt][2], ah[mt][3], uh[r][nt][0], uh[r][nt][1]);
                    mma_bf16(acc[mt][nt], al[mt][0], al[mt][1], al[mt][2], al[mt][3], uh[r][nt][0], uh[r][nt][1]);
                    mma_bf16(acc[mt][nt], ah[mt][0], ah[mt][1], ah[mt][2], ah[mt][3], ul[r][nt][0], ul[r][nt][1]);
                }
        }

        // ---- store per-warp 32x32 partials (zS reads of prev step done before
        //      this sync; zS region untouched during MMA phase)
        __syncthreads();
#pragma unroll
        for (int mt = 0; mt < 2; ++mt)
#pragma unroll
            for (int nt = 0; nt < 4; ++nt) {
                int m = mt * 16 + g;
                int n = nt * 8 + t4 * 2;
                *(float2*)(zS + w * ZROW + m * 36 + n) = make_float2(acc[mt][nt][0], acc[mt][nt][1]);
                *(float2*)(zS + w * ZROW + (m + 8) * 36 + n) = make_float2(acc[mt][nt][2], acc[mt][nt][3]);
            }
        __syncthreads();

        // ---- gates: owner sums the 8 partials (fixed order)
        float hn;
        {
            float z[4];
#pragma unroll
            for (int gi = 0; gi < 4; ++gi) {
                float s = 0.f;
#pragma unroll
                for (int w2 = 0; w2 < 8; ++w2)
                    s += zS[w2 * ZROW + om * 36 + gi * 8 + oj];
                z[gi] = s + xw[gi];
            }
            float si = 1.f / (1.f + expf(-z[0]));
            float sf = 1.f / (1.f + expf(-z[1]));
            float tg = tanhf(z[2]);
            float so = 1.f / (1.f + expf(-z[3]));
            creg = sf * creg + si * tg;
            hn = so * tanhf(creg);
        }

        // ---- pack + publish new h chunk (this block's 8 cols), then flag
        {
            float hh = bfhi(hn), hl = hn - hh;
            float ph = __shfl_xor_sync(0xffffffffu, hh, 1);
            float pl = __shfl_xor_sync(0xffffffffu, hl, 1);
            if (!(oj & 1)) {
                int kp = bx * 4 + (oj >> 1);
                uint32_t wh = packbf2(hh, ph);
                uint32_t wl = packbf2(hl, pl);
                g_hbf[(t + 1) & 1][0][om][kp] = wh;
                g_hbf[(t + 1) & 1][1][om][kp] = wl;
                size_t row = (size_t)om * TT + t;
                g_sqh[row * KP + kp] = wh;
                g_sql[row * KP + kp] = wl;
            }
            if (t == TT - 1) g_h[0][om * HH + ohcol] = hn;
        }
        __threadfence();               // release this thread's h writes
        __syncthreads();               // all threads' publishes done
        if (tid == 0) flags[bx] = t + 1;
        // no wait here — consumers poll per-slice at the top of the next step
    }

    // ---- write back cell state
    g_c[om * HH + ohcol] = creg;
}

// ---------------- launch ----------------
extern "C" void kernel_launch(void* const* d_in, const int* in_sizes, int n_in,
                              void* d_out, int out_size)
{
    const int*   x       = (const int*)d_in[0];
    const float* state_h = (const float*)d_in[1];
    const float* state_c = (const float*)d_in[2];
    const float* emb     = (const float*)d_in[3];
    const float* W       = (const float*)d_in[4];
    const float* U       = (const float*)d_in[5];
    const float* b       = (const float*)d_in[6];
    const float* dW      = (const float*)d_in[7];
    const float* db      = (const float*)d_in[8];
    float* out = (float*)d_out;

    float*    xW_ptr  = nullptr;
    uint32_t* sqh_ptr = nullptr;
    uint32_t* sql_ptr = nullptr;
    uint32_t* bhp_ptr = nullptr;
    uint32_t* blp_ptr = nullptr;
    cudaGetSymbolAddress((void**)&xW_ptr,  g_xW);
    cudaGetSymbolAddress((void**)&sqh_ptr, g_sqh);
    cudaGetSymbolAddress((void**)&sql_ptr, g_sql);
    cudaGetSymbolAddress((void**)&bhp_ptr, g_Bhp);
    cudaGetSymbolAddress((void**)&blp_ptr, g_Blp);

    // unconditional (no static guards); idempotent + capture-safe
    cudaFuncSetAttribute(lstm_scan_kernel,
                         cudaFuncAttributeMaxDynamicSharedMemorySize, SCAN_SMEM_BYTES);
    cudaFuncSetAttribute(bf16_gemm_kernel,
                         cudaFuncAttributeMaxDynamicSharedMemorySize, GEMM_SMEM_BYTES);

    // 1) load initial state (incl. packed bf16 h0) + reset flags
    init_state_kernel<<<64, 512>>>(state_h, state_c);

    // 1b) pre-split dense_W into packed bf16 hi/lo (pure streaming)
    split_b_kernel<<<8192, 256>>>(dW);

    // 2) xW = emb_table[x] @ W + b   (M=2048, N=4096, K=512, gathered A, fp32)
    {
        dim3 grid(G4H / 128, NROWS / 128);
        sgemm_kernel<true><<<grid, 256>>>(emb, x, W, b, xW_ptr, NROWS, G4H, EE, EE);
    }

    // 3) LSTM scan: persistent dataflow kernel (bf16x3, fragment LDG, slice flags)
    lstm_scan_kernel<<<NBLK, NTHR, SCAN_SMEM_BYTES>>>(U);

    // 4) logits = seq @ dense_W + dense_b  (bf16x3 tensor cores, double-buffered)
    {
        dim3 grid(VV / 128, NROWS / 128);
        bf16_gemm_kernel<<<grid, 256, GEMM_SMEM_BYTES>>>(
            sqh_ptr, sql_ptr, bhp_ptr, blp_ptr, db, out, NROWS, VV, HH);
    }

    // 5) final h, c appended after logits
    float* out_h = out + (size_t)NROWS * VV;       // 65,536,000
    float* out_c = out_h + BB * HH;                // +32,768
    write_state_kernel<<<64, 512>>>(out_h, out_c);
}

// round 14
// speedup vs baseline: 1.4039x; 1.0213x over previous
#include <cuda_runtime.h>
#include <cuda_bf16.h>
#include <math.h>
#include <stdint.h>

// Problem constants
#define VV 32000
#define EE 512
#define HH 1024
#define BB 32
#define TT 64
#define G4H (4 * HH)          // 4096
#define NROWS (BB * TT)       // 2048
#define KP 512                // packed k-pairs per row (HH/2)

#define NBLK 128              // persistent scan blocks
#define NTHR 256              // 8 warps

// scan smem (words): U-build transient (2*32*260) unions with zS (8*1156)
#define UBROW 260
#define ZROW 1156
#define SCAN_SMEM_WORDS (2*32*UBROW)
#define SCAN_SMEM_BYTES (SCAN_SMEM_WORDS * 4)   // 66,560 B

// GEMM smem word offsets (triple-buffered)
#define GA_H 0                // [3][2560]
#define GA_L 7680             // [3][2560]
#define GB_H 15360            // [3][2176]
#define GB_L 21888            // [3][2176]
#define GEMM_SMEM_WORDS 28416
#define GEMM_SMEM_BYTES (GEMM_SMEM_WORDS * 4)   // 113,664 B

// ---------------- scratch (no allocs allowed) ----------------
__device__ float    g_xW[NROWS * G4H];        // [b*T+t, 4H] input projections (+bias)
__device__ uint32_t g_sqh[(size_t)NROWS * KP];// seq packed bf16 hi pairs [row][kp]
__device__ uint32_t g_sql[(size_t)NROWS * KP];// seq packed bf16 lo pairs
__device__ float    g_h[2][BB * HH];          // final-h staging
__device__ float    g_c[BB * HH];             // cell state
__device__ int      g_flag[NBLK];             // per-block publish counters
__device__ uint32_t g_hbf[2][2][32][KP];      // packed bf16 h pairs [buf][hi/lo][m][kp]
__device__ uint32_t g_Bhp[(size_t)KP * VV];   // dense_W packed bf16 hi pairs [kp][n]
__device__ uint32_t g_Blp[(size_t)KP * VV];   // dense_W packed bf16 lo pairs

// ---------------- helpers ----------------
__device__ __forceinline__ uint32_t packbf2(float a, float b) {  // a -> low half (k even)
    __nv_bfloat162 p = __floats2bfloat162_rn(a, b);
    return *reinterpret_cast<uint32_t*>(&p);
}
__device__ __forceinline__ float bfhi(float x) {
    return __bfloat162float(__float2bfloat16_rn(x));
}
__device__ __forceinline__ void mma_bf16(float* c, uint32_t a0, uint32_t a1, uint32_t a2, uint32_t a3,
                                         uint32_t b0, uint32_t b1) {
    asm volatile(
        "mma.sync.aligned.m16n8k16.row.col.f32.bf16.bf16.f32 "
        "{%0,%1,%2,%3}, {%4,%5,%6,%7}, {%8,%9}, {%0,%1,%2,%3};"
        : "+f"(c[0]), "+f"(c[1]), "+f"(c[2]), "+f"(c[3])
        : "r"(a0), "r"(a1), "r"(a2), "r"(a3), "r"(b0), "r"(b1));
}
__device__ __forceinline__ void cp16(uint32_t smem_addr, const void* gmem) {
    asm volatile("cp.async.cg.shared.global [%0], [%1], 16;" :: "r"(smem_addr), "l"(gmem) : "memory");
}
#define CP_COMMIT asm volatile("cp.async.commit_group;" ::: "memory")
#define CP_WAIT0  asm volatile("cp.async.wait_group 0;" ::: "memory")
#define CP_WAIT1  asm volatile("cp.async.wait_group 1;" ::: "memory")
#define CP_WAIT2  asm volatile("cp.async.wait_group 2;" ::: "memory")

// ---------------- init / finalize ----------------
__global__ void init_state_kernel(const float* __restrict__ h0, const float* __restrict__ c0) {
    int i = blockIdx.x * blockDim.x + threadIdx.x;
    if (i < BB * HH) g_c[i] = c0[i];
    if (i < BB * HH / 2) {                 // pack h0 into g_hbf[0]
        int m = i >> 9;
        int kp = i & 511;
        float a = h0[m * HH + 2 * kp];
        float b = h0[m * HH + 2 * kp + 1];
        float ah = bfhi(a), bh = bfhi(b);
        g_hbf[0][0][m][kp] = packbf2(ah, bh);
        g_hbf[0][1][m][kp] = packbf2(a - ah, b - bh);
    }
    if (i < NBLK) g_flag[i] = 0;
}

__global__ void write_state_kernel(float* __restrict__ out_h, float* __restrict__ out_c) {
    int i = blockIdx.x * blockDim.x + threadIdx.x;
    if (i < BB * HH) {
        out_h[i] = g_h[0][i];
        out_c[i] = g_c[i];
    }
}

// ---------------- dense_W -> packed bf16 hi/lo [kp][n] ----------------
__global__ void split_b_kernel(const float* __restrict__ B) {
    const size_t tot = (size_t)KP * (VV / 4);
    size_t idx = (size_t)blockIdx.x * blockDim.x + threadIdx.x;
    const size_t stride = (size_t)gridDim.x * blockDim.x;
    for (; idx < tot; idx += stride) {
        int kp = (int)(idx / (VV / 4));
        int n4 = (int)(idx % (VV / 4)) * 4;
        float4 v0 = *(const float4*)(B + (size_t)(2 * kp) * VV + n4);
        float4 v1 = *(const float4*)(B + (size_t)(2 * kp + 1) * VV + n4);
        uint4 ho, lo;
        {
            float h0 = bfhi(v0.x), h1 = bfhi(v1.x);
            ho.x = packbf2(h0, h1); lo.x = packbf2(v0.x - h0, v1.x - h1);
        }
        {
            float h0 = bfhi(v0.y), h1 = bfhi(v1.y);
            ho.y = packbf2(h0, h1); lo.y = packbf2(v0.y - h0, v1.y - h1);
        }
        {
            float h0 = bfhi(v0.z), h1 = bfhi(v1.z);
            ho.z = packbf2(h0, h1); lo.z = packbf2(v0.z - h0, v1.z - h1);
        }
        {
            float h0 = bfhi(v0.w), h1 = bfhi(v1.w);
            ho.w = packbf2(h0, h1); lo.w = packbf2(v0.w - h0, v1.w - h1);
        }
        *(uint4*)(g_Bhp + (size_t)kp * VV + n4) = ho;
        *(uint4*)(g_Blp + (size_t)kp * VV + n4) = lo;
    }
}

// ---------------- bf16x3 GEMM (logits), cp.async triple-buffered ----------------
// Grid: (M/128 fast, N/128 slow) so consecutive blocks share the SAME B panel
// (B read from DRAM once per bn column; A is L2-resident).
__global__ __launch_bounds__(256, 1)
void bf16_gemm_kernel(const uint32_t* __restrict__ Ahp, const uint32_t* __restrict__ Alp,
                      const uint32_t* __restrict__ Bhp, const uint32_t* __restrict__ Blp,
                      const float* __restrict__ bias, float* __restrict__ C,
                      int M, int N, int K)
{
    extern __shared__ uint32_t gsm[];
    const int tid = threadIdx.x;
    const int lane = tid & 31, wid = tid >> 5;
    const int wr = wid >> 2, wc = wid & 3;
    const int g = lane >> 2, t4 = lane & 3;
    const int bm = blockIdx.x * 128, bn = blockIdx.y * 128;   // bm = FAST axis
    const int kprow = K >> 1;   // 512
    const uint32_t smB = (uint32_t)__cvta_generic_to_shared(gsm);

    float acc[4][4][4];
#pragma unroll
    for (int i = 0; i < 4; ++i)
#pragma unroll
        for (int j = 0; j < 4; ++j)
#pragma unroll
            for (int r = 0; r < 4; ++r) acc[i][j][r] = 0.f;

    const int ntiles = K / 32;  // 32

    auto issue = [&](int tile, int buf) {
        int ktp = tile * 16;
#pragma unroll
        for (int i = 0; i < 2; ++i) {
            int id = tid + i * 256;
            int m = id >> 2, kp4 = id & 3;
            const uint32_t* sH = Ahp + (size_t)(bm + m) * kprow + ktp + kp4 * 4;
            const uint32_t* sL = Alp + (size_t)(bm + m) * kprow + ktp + kp4 * 4;
            cp16(smB + (GA_H + buf * 2560 + m * 20 + kp4 * 4) * 4, sH);
            cp16(smB + (GA_L + buf * 2560 + m * 20 + kp4 * 4) * 4, sL);
        }
#pragma unroll
        for (int i = 0; i < 2; ++i) {
            int id = tid + i * 256;
            int kr = id >> 5, n4 = (id & 31) * 4;
            const uint32_t* sH = Bhp + (size_t)(ktp + kr) * N + bn + n4;
            const uint32_t* sL = Blp + (size_t)(ktp + kr) * N + bn + n4;
            cp16(smB + (GB_H + buf * 2176 + kr * 136 + n4) * 4, sH);
            cp16(smB + (GB_L + buf * 2176 + kr * 136 + n4) * 4, sL);
        }
        CP_COMMIT;
    };

    issue(0, 0);
    issue(1, 1);
    for (int tile = 0; tile < ntiles; ++tile) {
        int buf = tile % 3;
        if (tile + 2 < ntiles) issue(tile + 2, (tile + 2) % 3);
        // wait until tile's group is complete
        if (tile + 2 < ntiles)      { CP_WAIT2; }
        else if (tile + 1 < ntiles) { CP_WAIT1; }
        else                        { CP_WAIT0; }
        __syncthreads();

        const uint32_t* AhT = gsm + GA_H + buf * 2560;
        const uint32_t* AlT = gsm + GA_L + buf * 2560;
        const uint32_t* BhT = gsm + GB_H + buf * 2176;
        const uint32_t* BlT = gsm + GB_L + buf * 2176;
#pragma unroll
        for (int s = 0; s < 2; ++s) {
            const int kb = s * 8 + t4;
            uint32_t ah[4][4], al[4][4];
#pragma unroll
            for (int mt = 0; mt < 4; ++mt) {
                int r0 = wr * 64 + mt * 16 + g;
                ah[mt][0] = AhT[r0 * 20 + kb];
                ah[mt][1] = AhT[(r0 + 8) * 20 + kb];
                ah[mt][2] = AhT[r0 * 20 + kb + 4];
                ah[mt][3] = AhT[(r0 + 8) * 20 + kb + 4];
                al[mt][0] = AlT[r0 * 20 + kb];
                al[mt][1] = AlT[(r0 + 8) * 20 + kb];
                al[mt][2] = AlT[r0 * 20 + kb + 4];
                al[mt][3] = AlT[(r0 + 8) * 20 + kb + 4];
            }
#pragma unroll
            for (int nt = 0; nt < 4; ++nt) {
                int c0 = wc * 32 + nt * 8 + g;
                uint32_t bh0 = BhT[kb * 136 + c0];
                uint32_t bh1 = BhT[(kb + 4) * 136 + c0];
                uint32_t bl0 = BlT[kb * 136 + c0];
                uint32_t bl1 = BlT[(kb + 4) * 136 + c0];
#pragma unroll
                for (int mt = 0; mt < 4; ++mt) {
                    mma_bf16(acc[mt][nt], ah[mt][0], ah[mt][1], ah[mt][2], ah[mt][3], bh0, bh1);
                    mma_bf16(acc[mt][nt], al[mt][0], al[mt][1], al[mt][2], al[mt][3], bh0, bh1);
                    mma_bf16(acc[mt][nt], ah[mt][0], ah[mt][1], ah[mt][2], ah[mt][3], bl0, bl1);
                }
            }
        }
        __syncthreads();
    }

#pragma unroll
    for (int mt = 0; mt < 4; ++mt) {
        int r0 = bm + wr * 64 + mt * 16 + g;
#pragma unroll
        for (int nt = 0; nt < 4; ++nt) {
            int col = bn + wc * 32 + nt * 8 + 2 * t4;
            float b0 = bias[col], b1 = bias[col + 1];
            float2 v0 = make_float2(acc[mt][nt][0] + b0, acc[mt][nt][1] + b1);
            float2 v1 = make_float2(acc[mt][nt][2] + b0, acc[mt][nt][3] + b1);
            *(float2*)(C + (size_t)r0 * N + col) = v0;
            *(float2*)(C + (size_t)(r0 + 8) * N + col) = v1;
        }
    }
}

// ---------------- fp32 SGEMM (xW, gathered) ----------------
template <bool GATHER>
__global__ __launch_bounds__(256, 2)
void sgemm_kernel(const float* __restrict__ A, const int* __restrict__ rowidx,
                  const float* __restrict__ B, const float* __restrict__ bias,
                  float* __restrict__ C, int M, int N, int K, int lda)
{
    constexpr int BM = 128, BN = 128, BK = 8, TM = 8, TN = 8;
    __shared__ float As[BK][BM];
    __shared__ float Bs[BK][BN];

    const int brow = blockIdx.y;
    const int bcol = blockIdx.x;
    const int tid = threadIdx.x;
    const int tx = tid % 16;
    const int ty = tid / 16;

    float acc[TM][TN];
#pragma unroll
    for (int i = 0; i < TM; ++i)
#pragma unroll
        for (int j = 0; j < TN; ++j) acc[i][j] = 0.f;

    const int a_r = tid >> 1;
    const int a_k = (tid & 1) * 4;
    const int b_k = tid >> 5;
    const int b_c = (tid & 31) * 4;

    const int grow = brow * BM + a_r;
    const float* Arow;
    if (GATHER) Arow = A + (size_t)rowidx[grow] * lda;
    else        Arow = A + (size_t)grow * lda;
    const float* Bbase = B + (size_t)bcol * BN;

    float4 av = *(const float4*)(Arow + a_k);
    float4 bv = *(const float4*)(Bbase + (size_t)b_k * N + b_c);

    for (int kt = 0; kt < K; kt += BK) {
        As[a_k + 0][a_r] = av.x;
        As[a_k + 1][a_r] = av.y;
        As[a_k + 2][a_r] = av.z;
        As[a_k + 3][a_r] = av.w;
        *(float4*)(&Bs[b_k][b_c]) = bv;
        __syncthreads();
        if (kt + BK < K) {
            av = *(const float4*)(Arow + kt + BK + a_k);
            bv = *(const float4*)(Bbase + (size_t)(kt + BK + b_k) * N + b_c);
        }
#pragma unroll
        for (int k = 0; k < BK; ++k) {
            float ra[TM], rb[TN];
#pragma unroll
            for (int i = 0; i < TM; ++i) ra[i] = As[k][ty * TM + i];
#pragma unroll
            for (int j = 0; j < TN; ++j) rb[j] = Bs[k][tx * TN + j];
#pragma unroll
            for (int i = 0; i < TM; ++i)
#pragma unroll
                for (int j = 0; j < TN; ++j)
                    acc[i][j] += ra[i] * rb[j];
        }
        __syncthreads();
    }

    const int ccol0 = bcol * BN + tx * TN;
#pragma unroll
    for (int i = 0; i < TM; ++i) {
        size_t r = (size_t)(brow * BM + ty * TM + i);
        float* crow = C + r * (size_t)N + ccol0;
#pragma unroll
        for (int j = 0; j < TN; j += 4) {
            float4 v;
            v.x = acc[i][j + 0] + bias[ccol0 + j + 0];
            v.y = acc[i][j + 1] + bias[ccol0 + j + 1];
            v.z = acc[i][j + 2] + bias[ccol0 + j + 2];
            v.w = acc[i][j + 3] + bias[ccol0 + j + 3];
            *(float4*)(crow + j) = v;
        }
    }
}

// ---------------- persistent LSTM scan (bf16x3 TC, dataflow, pipelined slices) ----------------
// 128 blocks x 256 threads. Block bx owns 32 z-cols. U B-fragments in registers.
// Warps LDG A-fragments straight from g_hbf; per-slice producer-flag waits.
// Slice loop is software-pipelined: poll+load slice r+1 issued before MMAs of slice r.
__global__ __launch_bounds__(NTHR, 1)
void lstm_scan_kernel(const float* __restrict__ U)
{
    extern __shared__ uint32_t smw[];
    float* zS = (float*)smw;           // [8 w][ZROW] (after U-build phase)

    const int bx = blockIdx.x;
    const int tid = threadIdx.x;
    const int w = tid >> 5;
    const int lane = tid & 31;
    const int g = lane >> 2;
    const int t4 = lane & 3;

    // ---- one-time: build U B-fragments in registers (transient smem chunks)
    uint32_t uh[8][4][2], ul[8][4][2];
    {
        uint32_t* ubh = smw;
        uint32_t* ubl = smw + 32 * UBROW;
        for (int ch = 0; ch < 2; ++ch) {
            __syncthreads();
            for (int i = tid; i < 2048; i += NTHR) {
                int kp = i >> 3;
                int c4 = (i & 7) * 4;
                int gg = c4 >> 3, jj = c4 & 7;
                int gcol = gg * HH + bx * 8 + jj;
                int k0 = (ch * 256 + kp) * 2;
                float4 v0 = *(const float4*)(U + (size_t)k0 * G4H + gcol);
                float4 v1 = *(const float4*)(U + (size_t)(k0 + 1) * G4H + gcol);
                const float a0[4] = {v0.x, v0.y, v0.z, v0.w};
                const float a1[4] = {v1.x, v1.y, v1.z, v1.w};
#pragma unroll
                for (int q = 0; q < 4; ++q) {
                    float h0 = bfhi(a0[q]), l0 = a0[q] - h0;
                    float h1 = bfhi(a1[q]), l1 = a1[q] - h1;
                    ubh[(c4 + q) * UBROW + kp] = packbf2(h0, h1);
                    ubl[(c4 + q) * UBROW + kp] = packbf2(l0, l1);
                }
            }
            __syncthreads();
#pragma unroll
            for (int rr = 0; rr < 4; ++rr) {
                int r = ch * 4 + rr;
                int s = w + r * 8;
                int kwl = s * 8 - ch * 256;
#pragma unroll
                for (int nt = 0; nt < 4; ++nt) {
                    int ub = (nt * 8 + g) * UBROW + kwl + t4;
                    uh[r][nt][0] = ubh[ub];
                    uh[r][nt][1] = ubh[ub + 4];
                    ul[r][nt][0] = ubl[ub];
                    ul[r][nt][1] = ubl[ub + 4];
                }
            }
        }
        __syncthreads();
    }

    // ---- cell state: thread owns (om, oj)
    const int om = tid >> 3;
    const int oj = tid & 7;
    const int ohcol = bx * 8 + oj;
    float creg = g_c[om * HH + ohcol];

    volatile int* flags = (volatile int*)g_flag;

    for (int t = 0; t < TT; ++t) {
        // prefetch xW for the gate phase
        float xw[4];
        {
            const float* xwp = g_xW + (size_t)(om * TT + t) * G4H + ohcol;
#pragma unroll
            for (int gg = 0; gg < 4; ++gg) xw[gg] = xwp[gg * HH];
        }

        const uint32_t* Hsrc = &g_hbf[t & 1][0][0][0];
        const uint32_t* Lsrc = &g_hbf[t & 1][1][0][0];

        float acc[2][4][4];
#pragma unroll
        for (int mt = 0; mt < 2; ++mt)
#pragma unroll
            for (int nt = 0; nt < 4; ++nt)
#pragma unroll
                for (int r = 0; r < 4; ++r) acc[mt][nt][r] = 0.f;

        uint32_t ah[2][2][4], al[2][2][4];   // [buf][mt][reg]

        // prologue: wait + load slice 0
        {
            const int s = w;
            if (lane < 2) { while (flags[2 * s + lane] < t) { } }
            __syncwarp();
#pragma unroll
            for (int mt = 0; mt < 2; ++mt) {
                int base = (mt * 16 + g) * KP + s * 8 + t4;
                ah[0][mt][0] = Hsrc[base];
                ah[0][mt][1] = Hsrc[base + 8 * KP];
                ah[0][mt][2] = Hsrc[base + 4];
                ah[0][mt][3] = Hsrc[base + 8 * KP + 4];
                al[0][mt][0] = Lsrc[base];
                al[0][mt][1] = Lsrc[base + 8 * KP];
                al[0][mt][2] = Lsrc[base + 4];
                al[0][mt][3] = Lsrc[base + 8 * KP + 4];
            }
        }

#pragma unroll
        for (int r = 0; r < 8; ++r) {
            const int cur = r & 1;
            // pipeline: poll + issue loads for slice r+1 before computing slice r
            if (r < 7) {
                const int s = w + (r + 1) * 8;
                if (lane < 2) { while (flags[2 * s + lane] < t) { } }
                __syncwarp();
                const int nxt = cur ^ 1;
#pragma unroll
                for (int mt = 0; mt < 2; ++mt) {
                    int base = (mt * 16 + g) * KP + s * 8 + t4;
                    ah[nxt][mt][0] = Hsrc[base];
                    ah[nxt][mt][1] = Hsrc[base + 8 * KP];
                    ah[nxt][mt][2] = Hsrc[base + 4];
                    ah[nxt][mt][3] = Hsrc[base + 8 * KP + 4];
                    al[nxt][mt][0] = Lsrc[base];
                    al[nxt][mt][1] = Lsrc[base + 8 * KP];
                    al[nxt][mt][2] = Lsrc[base + 4];
                    al[nxt][mt][3] = Lsrc[base + 8 * KP + 4];
                }
            }
#pragma unroll
            for (int mt = 0; mt < 2; ++mt)
#pragma unroll
                for (int nt = 0; nt < 4; ++nt) {
                    mma_bf16(acc[mt][nt], ah[cur][mt][0], ah[cur][mt][1], ah[cur][mt][2], ah[cur][mt][3],
                             uh[r][nt][0], uh[r][nt][1]);
                    mma_bf16(acc[mt][nt], al[cur][mt][0], al[cur][mt][1], al[cur][mt][2], al[cur][mt][3],
                             uh[r][nt][0], uh[r][nt][1]);
                    mma_bf16(acc[mt][nt], ah[cur][mt][0], ah[cur][mt][1], ah[cur][mt][2], ah[cur][mt][3],
                             ul[r][nt][0], ul[r][nt][1]);
                }
        }

        // ---- store per-warp 32x32 partials
        __syncthreads();
#pragma unroll
        for (int mt = 0; mt < 2; ++mt)
#pragma unroll
            for (int nt = 0; nt < 4; ++nt) {
                int m = mt * 16 + g;
                int n = nt * 8 + t4 * 2;
                *(float2*)(zS + w * ZROW + m * 36 + n) = make_float2(acc[mt][nt][0], acc[mt][nt][1]);
                *(float2*)(zS + w * ZROW + (m + 8) * 36 + n) = make_float2(acc[mt][nt][2], acc[mt][nt][3]);
            }
        __syncthreads();

        // ---- gates: owner sums the 8 partials (fixed order)
        float hn;
        {
            float z[4];
#pragma unroll
            for (int gi = 0; gi < 4; ++gi) {
                float s = 0.f;
#pragma unroll
                for (int w2 = 0; w2 < 8; ++w2)
                    s += zS[w2 * ZROW + om * 36 + gi * 8 + oj];
                z[gi] = s + xw[gi];
            }
            float si = 1.f / (1.f + expf(-z[0]));
            float sf = 1.f / (1.f + expf(-z[1]));
            float tg = tanhf(z[2]);
            float so = 1.f / (1.f + expf(-z[3]));
            creg = sf * creg + si * tg;
            hn = so * tanhf(creg);
        }

        // ---- pack + publish new h chunk (this block's 8 cols), then flag
        {
            float hh = bfhi(hn), hl = hn - hh;
            float ph = __shfl_xor_sync(0xffffffffu, hh, 1);
            float pl = __shfl_xor_sync(0xffffffffu, hl, 1);
            if (!(oj & 1)) {
                int kp = bx * 4 + (oj >> 1);
                uint32_t wh = packbf2(hh, ph);
                uint32_t wl = packbf2(hl, pl);
                g_hbf[(t + 1) & 1][0][om][kp] = wh;
                g_hbf[(t + 1) & 1][1][om][kp] = wl;
                size_t row = (size_t)om * TT + t;
                g_sqh[row * KP + kp] = wh;
                g_sql[row * KP + kp] = wl;
            }
            if (t == TT - 1) g_h[0][om * HH + ohcol] = hn;
        }
        __threadfence();               // release this thread's h writes
        __syncthreads();               // all threads' publishes done
        if (tid == 0) flags[bx] = t + 1;
    }

    // ---- write back cell state
    g_c[om * HH + ohcol] = creg;
}

// ---------------- launch ----------------
extern "C" void kernel_launch(void* const* d_in, const int* in_sizes, int n_in,
                              void* d_out, int out_size)
{
    const int*   x       = (const int*)d_in[0];
    const float* state_h = (const float*)d_in[1];
    const float* state_c = (const float*)d_in[2];
    const float* emb     = (const float*)d_in[3];
    const float* W       = (const float*)d_in[4];
    const float* U       = (const float*)d_in[5];
    const float* b       = (const float*)d_in[6];
    const float* dW      = (const float*)d_in[7];
    const float* db      = (const float*)d_in[8];
    float* out = (float*)d_out;

    float*    xW_ptr  = nullptr;
    uint32_t* sqh_ptr = nullptr;
    uint32_t* sql_ptr = nullptr;
    uint32_t* bhp_ptr = nullptr;
    uint32_t* blp_ptr = nullptr;
    cudaGetSymbolAddress((void**)&xW_ptr,  g_xW);
    cudaGetSymbolAddress((void**)&sqh_ptr, g_sqh);
    cudaGetSymbolAddress((void**)&sql_ptr, g_sql);
    cudaGetSymbolAddress((void**)&bhp_ptr, g_Bhp);
    cudaGetSymbolAddress((void**)&blp_ptr, g_Blp);

    // unconditional (no static guards); idempotent + capture-safe
    cudaFuncSetAttribute(lstm_scan_kernel,
                         cudaFuncAttributeMaxDynamicSharedMemorySize, SCAN_SMEM_BYTES);
    cudaFuncSetAttribute(bf16_gemm_kernel,
                         cudaFuncAttributeMaxDynamicSharedMemorySize, GEMM_SMEM_BYTES);

    // 1) load initial state (incl. packed bf16 h0) + reset flags
    init_state_kernel<<<64, 512>>>(state_h, state_c);

    // 1b) pre-split dense_W into packed bf16 hi/lo (pure streaming)
    split_b_kernel<<<8192, 256>>>(dW);

    // 2) xW = emb_table[x] @ W + b   (M=2048, N=4096, K=512, gathered A, fp32)
    {
        dim3 grid(G4H / 128, NROWS / 128);
        sgemm_kernel<true><<<grid, 256>>>(emb, x, W, b, xW_ptr, NROWS, G4H, EE, EE);
    }

    // 3) LSTM scan: persistent dataflow kernel (pipelined slice loads)
    lstm_scan_kernel<<<NBLK, NTHR, SCAN_SMEM_BYTES>>>(U);

    // 4) logits = seq @ dense_W + dense_b  (bf16x3, bm-fast grid, 3-stage pipeline)
    {
        dim3 grid(NROWS / 128, VV / 128);
        bf16_gemm_kernel<<<grid, 256, GEMM_SMEM_BYTES>>>(
            sqh_ptr, sql_ptr, bhp_ptr, blp_ptr, db, out, NROWS, VV, HH);
    }

    // 5) final h, c appended after logits
    float* out_h = out + (size_t)NROWS * VV;       // 65,536,000
    float* out_c = out_h + BB * HH;                // +32,768
    write_state_kernel<<<64, 512>>>(out_h, out_c);
}

// round 15
// speedup vs baseline: 1.5736x; 1.1209x over previous
#include <cuda_runtime.h>
#include <cuda_bf16.h>
#include <math.h>
#include <stdint.h>

// Problem constants
#define VV 32000
#define EE 512
#define HH 1024
#define BB 32
#define TT 64
#define G4H (4 * HH)          // 4096
#define NROWS (BB * TT)       // 2048
#define KP 512                // packed k-pairs per row (HH/2)

#define NBLK 128              // persistent scan blocks
#define NTHR 256              // 8 warps

// scan smem (words): U-build transient (2*32*260) unions with zS (8*1156)
#define UBROW 260
#define ZROW 1156
#define SCAN_SMEM_WORDS (2*32*UBROW)
#define SCAN_SMEM_BYTES (SCAN_SMEM_WORDS * 4)   // 66,560 B

// GEMM smem word offsets (double-buffered -> 2 blocks/SM)
#define GA_H 0                // [2][2560]
#define GA_L 5120             // [2][2560]
#define GB_H 10240            // [2][2176]
#define GB_L 14592            // [2][2176]
#define GEMM_SMEM_WORDS 18944
#define GEMM_SMEM_BYTES (GEMM_SMEM_WORDS * 4)   // 75,776 B  (x2 = 151,552 <= 227KB)

// ---------------- scratch (no allocs allowed) ----------------
__device__ float    g_xW[NROWS * G4H];        // [b*T+t, 4H] input projections (+bias)
__device__ uint32_t g_sqh[(size_t)NROWS * KP];// seq packed bf16 hi pairs [row][kp]
__device__ uint32_t g_sql[(size_t)NROWS * KP];// seq packed bf16 lo pairs
__device__ float    g_h[2][BB * HH];          // final-h staging
__device__ float    g_c[BB * HH];             // cell state
__device__ int      g_flag[NBLK];             // per-block publish counters
__device__ uint32_t g_hbf[2][2][32][KP];      // packed bf16 h pairs [buf][hi/lo][m][kp]
__device__ uint32_t g_Bhp[(size_t)KP * VV];   // dense_W packed bf16 hi pairs [kp][n]
__device__ uint32_t g_Blp[(size_t)KP * VV];   // dense_W packed bf16 lo pairs

// ---------------- helpers ----------------
__device__ __forceinline__ uint32_t packbf2(float a, float b) {  // a -> low half (k even)
    __nv_bfloat162 p = __floats2bfloat162_rn(a, b);
    return *reinterpret_cast<uint32_t*>(&p);
}
__device__ __forceinline__ float bfhi(float x) {
    return __bfloat162float(__float2bfloat16_rn(x));
}
__device__ __forceinline__ void mma_bf16(float* c, uint32_t a0, uint32_t a1, uint32_t a2, uint32_t a3,
                                         uint32_t b0, uint32_t b1) {
    asm volatile(
        "mma.sync.aligned.m16n8k16.row.col.f32.bf16.bf16.f32 "
        "{%0,%1,%2,%3}, {%4,%5,%6,%7}, {%8,%9}, {%0,%1,%2,%3};"
        : "+f"(c[0]), "+f"(c[1]), "+f"(c[2]), "+f"(c[3])
        : "r"(a0), "r"(a1), "r"(a2), "r"(a3), "r"(b0), "r"(b1));
}
__device__ __forceinline__ void ldsm4(uint32_t* r, uint32_t addr) {
    asm volatile("ldmatrix.sync.aligned.m8n8.x4.shared.b16 {%0,%1,%2,%3}, [%4];"
        : "=r"(r[0]), "=r"(r[1]), "=r"(r[2]), "=r"(r[3]) : "r"(addr));
}
__device__ __forceinline__ void cp16(uint32_t smem_addr, const void* gmem) {
    asm volatile("cp.async.cg.shared.global [%0], [%1], 16;" :: "r"(smem_addr), "l"(gmem) : "memory");
}
#define CP_COMMIT asm volatile("cp.async.commit_group;" ::: "memory")
#define CP_WAIT0  asm volatile("cp.async.wait_group 0;" ::: "memory")
#define CP_WAIT1  asm volatile("cp.async.wait_group 1;" ::: "memory")

// ---------------- init / finalize ----------------
__global__ void init_state_kernel(const float* __restrict__ h0, const float* __restrict__ c0) {
    int i = blockIdx.x * blockDim.x + threadIdx.x;
    if (i < BB * HH) g_c[i] = c0[i];
    if (i < BB * HH / 2) {                 // pack h0 into g_hbf[0]
        int m = i >> 9;
        int kp = i & 511;
        float a = h0[m * HH + 2 * kp];
        float b = h0[m * HH + 2 * kp + 1];
        float ah = bfhi(a), bh = bfhi(b);
        g_hbf[0][0][m][kp] = packbf2(ah, bh);
        g_hbf[0][1][m][kp] = packbf2(a - ah, b - bh);
    }
    if (i < NBLK) g_flag[i] = 0;
}

__global__ void write_state_kernel(float* __restrict__ out_h, float* __restrict__ out_c) {
    int i = blockIdx.x * blockDim.x + threadIdx.x;
    if (i < BB * HH) {
        out_h[i] = g_h[0][i];
        out_c[i] = g_c[i];
    }
}

// ---------------- dense_W -> packed bf16 hi/lo [kp][n] ----------------
__global__ void split_b_kernel(const float* __restrict__ B) {
    const size_t tot = (size_t)KP * (VV / 4);
    size_t idx = (size_t)blockIdx.x * blockDim.x + threadIdx.x;
    const size_t stride = (size_t)gridDim.x * blockDim.x;
    for (; idx < tot; idx += stride) {
        int kp = (int)(idx / (VV / 4));
        int n4 = (int)(idx % (VV / 4)) * 4;
        float4 v0 = *(const float4*)(B + (size_t)(2 * kp) * VV + n4);
        float4 v1 = *(const float4*)(B + (size_t)(2 * kp + 1) * VV + n4);
        uint4 ho, lo;
        {
            float h0 = bfhi(v0.x), h1 = bfhi(v1.x);
            ho.x = packbf2(h0, h1); lo.x = packbf2(v0.x - h0, v1.x - h1);
        }
        {
            float h0 = bfhi(v0.y), h1 = bfhi(v1.y);
            ho.y = packbf2(h0, h1); lo.y = packbf2(v0.y - h0, v1.y - h1);
        }
        {
            float h0 = bfhi(v0.z), h1 = bfhi(v1.z);
            ho.z = packbf2(h0, h1); lo.z = packbf2(v0.z - h0, v1.z - h1);
        }
        {
            float h0 = bfhi(v0.w), h1 = bfhi(v1.w);
            ho.w = packbf2(h0, h1); lo.w = packbf2(v0.w - h0, v1.w - h1);
        }
        *(uint4*)(g_Bhp + (size_t)kp * VV + n4) = ho;
        *(uint4*)(g_Blp + (size_t)kp * VV + n4) = lo;
    }
}

// ---------------- bf16x3 GEMM (logits): 2 blocks/SM + ldmatrix A frags ----------------
// Grid: (M/128 fast, N/128 slow). Double-buffered cp.async.
__global__ __launch_bounds__(256, 2)
void bf16_gemm_kernel(const uint32_t* __restrict__ Ahp, const uint32_t* __restrict__ Alp,
                      const uint32_t* __restrict__ Bhp, const uint32_t* __restrict__ Blp,
                      const float* __restrict__ bias, float* __restrict__ C,
                      int M, int N, int K)
{
    extern __shared__ uint32_t gsm[];
    const int tid = threadIdx.x;
    const int lane = tid & 31, wid = tid >> 5;
    const int wr = wid >> 2, wc = wid & 3;
    const int g = lane >> 2, t4 = lane & 3;
    const int bm = blockIdx.x * 128, bn = blockIdx.y * 128;   // bm = FAST axis
    const int kprow = K >> 1;   // 512
    const uint32_t smB = (uint32_t)__cvta_generic_to_shared(gsm);

    // ldmatrix lane addressing (row within 16-row tile, word offset 0 or 4)
    const int lrow = lane & 15;
    const int lcol = (lane >> 4) * 4;

    float acc[4][4][4];
#pragma unroll
    for (int i = 0; i < 4; ++i)
#pragma unroll
        for (int j = 0; j < 4; ++j)
#pragma unroll
            for (int r = 0; r < 4; ++r) acc[i][j][r] = 0.f;

    const int ntiles = K / 32;  // 32

    auto issue = [&](int tile, int buf) {
        int ktp = tile * 16;
#pragma unroll
        for (int i = 0; i < 2; ++i) {
            int id = tid + i * 256;
            int m = id >> 2, kp4 = id & 3;
            const uint32_t* sH = Ahp + (size_t)(bm + m) * kprow + ktp + kp4 * 4;
            const uint32_t* sL = Alp + (size_t)(bm + m) * kprow + ktp + kp4 * 4;
            cp16(smB + (GA_H + buf * 2560 + m * 20 + kp4 * 4) * 4, sH);
            cp16(smB + (GA_L + buf * 2560 + m * 20 + kp4 * 4) * 4, sL);
        }
#pragma unroll
        for (int i = 0; i < 2; ++i) {
            int id = tid + i * 256;
            int kr = id >> 5, n4 = (id & 31) * 4;
            const uint32_t* sH = Bhp + (size_t)(ktp + kr) * N + bn + n4;
            const uint32_t* sL = Blp + (size_t)(ktp + kr) * N + bn + n4;
            cp16(smB + (GB_H + buf * 2176 + kr * 136 + n4) * 4, sH);
            cp16(smB + (GB_L + buf * 2176 + kr * 136 + n4) * 4, sL);
        }
        CP_COMMIT;
    };

    issue(0, 0);
    for (int tile = 0; tile < ntiles; ++tile) {
        int buf = tile & 1;
        if (tile + 1 < ntiles) { issue(tile + 1, buf ^ 1); CP_WAIT1; }
        else                   { CP_WAIT0; }
        __syncthreads();

        const uint32_t baseAH = GA_H + buf * 2560;
        const uint32_t baseAL = GA_L + buf * 2560;
        const uint32_t* BhT = gsm + GB_H + buf * 2176;
        const uint32_t* BlT = gsm + GB_L + buf * 2176;
#pragma unroll
        for (int s = 0; s < 2; ++s) {
            const int kwb = s * 8;
            const int kb = kwb + t4;
            uint32_t ah[4][4], al[4][4];
#pragma unroll
            for (int mt = 0; mt < 4; ++mt) {
                uint32_t roff = (uint32_t)((wr * 64 + mt * 16 + lrow) * 20 + kwb + lcol);
                ldsm4(ah[mt], smB + (baseAH + roff) * 4);
                ldsm4(al[mt], smB + (baseAL + roff) * 4);
            }
#pragma unroll
            for (int nt = 0; nt < 4; ++nt) {
                int c0 = wc * 32 + nt * 8 + g;
                uint32_t bh0 = BhT[kb * 136 + c0];
                uint32_t bh1 = BhT[(kb + 4) * 136 + c0];
                uint32_t bl0 = BlT[kb * 136 + c0];
                uint32_t bl1 = BlT[(kb + 4) * 136 + c0];
#pragma unroll
                for (int mt = 0; mt < 4; ++mt) {
                    mma_bf16(acc[mt][nt], ah[mt][0], ah[mt][1], ah[mt][2], ah[mt][3], bh0, bh1);
                    mma_bf16(acc[mt][nt], al[mt][0], al[mt][1], al[mt][2], al[mt][3], bh0, bh1);
                    mma_bf16(acc[mt][nt], ah[mt][0], ah[mt][1], ah[mt][2], ah[mt][3], bl0, bl1);
                }
            }
        }
        __syncthreads();
    }

#pragma unroll
    for (int mt = 0; mt < 4; ++mt) {
        int r0 = bm + wr * 64 + mt * 16 + g;
#pragma unroll
        for (int nt = 0; nt < 4; ++nt) {
            int col = bn + wc * 32 + nt * 8 + 2 * t4;
            float b0 = bias[col], b1 = bias[col + 1];
            float2 v0 = make_float2(acc[mt][nt][0] + b0, acc[mt][nt][1] + b1);
            float2 v1 = make_float2(acc[mt][nt][2] + b0, acc[mt][nt][3] + b1);
            *(float2*)(C + (size_t)r0 * N + col) = v0;
            *(float2*)(C + (size_t)(r0 + 8) * N + col) = v1;
        }
    }
}

// ---------------- fp32 SGEMM (xW, gathered) ----------------
template <bool GATHER>
__global__ __launch_bounds__(256, 2)
void sgemm_kernel(const float* __restrict__ A, const int* __restrict__ rowidx,
                  const float* __restrict__ B, const float* __restrict__ bias,
                  float* __restrict__ C, int M, int N, int K, int lda)
{
    constexpr int BM = 128, BN = 128, BK = 8, TM = 8, TN = 8;
    __shared__ float As[BK][BM];
    __shared__ float Bs[BK][BN];

    const int brow = blockIdx.y;
    const int bcol = blockIdx.x;
    const int tid = threadIdx.x;
    const int tx = tid % 16;
    const int ty = tid / 16;

    float acc[TM][TN];
#pragma unroll
    for (int i = 0; i < TM; ++i)
#pragma unroll
        for (int j = 0; j < TN; ++j) acc[i][j] = 0.f;

    const int a_r = tid >> 1;
    const int a_k = (tid & 1) * 4;
    const int b_k = tid >> 5;
    const int b_c = (tid & 31) * 4;

    const int grow = brow * BM + a_r;
    const float* Arow;
    if (GATHER) Arow = A + (size_t)rowidx[grow] * lda;
    else        Arow = A + (size_t)grow * lda;
    const float* Bbase = B + (size_t)bcol * BN;

    float4 av = *(const float4*)(Arow + a_k);
    float4 bv = *(const float4*)(Bbase + (size_t)b_k * N + b_c);

    for (int kt = 0; kt < K; kt += BK) {
        As[a_k + 0][a_r] = av.x;
        As[a_k + 1][a_r] = av.y;
        As[a_k + 2][a_r] = av.z;
        As[a_k + 3][a_r] = av.w;
        *(float4*)(&Bs[b_k][b_c]) = bv;
        __syncthreads();
        if (kt + BK < K) {
            av = *(const float4*)(Arow + kt + BK + a_k);
            bv = *(const float4*)(Bbase + (size_t)(kt + BK + b_k) * N + b_c);
        }
#pragma unroll
        for (int k = 0; k < BK; ++k) {
            float ra[TM], rb[TN];
#pragma unroll
            for (int i = 0; i < TM; ++i) ra[i] = As[k][ty * TM + i];
#pragma unroll
            for (int j = 0; j < TN; ++j) rb[j] = Bs[k][tx * TN + j];
#pragma unroll
            for (int i = 0; i < TM; ++i)
#pragma unroll
                for (int j = 0; j < TN; ++j)
                    acc[i][j] += ra[i] * rb[j];
        }
        __syncthreads();
    }

    const int ccol0 = bcol * BN + tx * TN;
#pragma unroll
    for (int i = 0; i < TM; ++i) {
        size_t r = (size_t)(brow * BM + ty * TM + i);
        float* crow = C + r * (size_t)N + ccol0;
#pragma unroll
        for (int j = 0; j < TN; j += 4) {
            float4 v;
            v.x = acc[i][j + 0] + bias[ccol0 + j + 0];
            v.y = acc[i][j + 1] + bias[ccol0 + j + 1];
            v.z = acc[i][j + 2] + bias[ccol0 + j + 2];
            v.w = acc[i][j + 3] + bias[ccol0 + j + 3];
            *(float4*)(crow + j) = v;
        }
    }
}

// ---------------- persistent LSTM scan (bf16x3 TC, dataflow, pipelined slices) ----------------
// (unchanged from R14 — measured 671 us)
__global__ __launch_bounds__(NTHR, 1)
void lstm_scan_kernel(const float* __restrict__ U)
{
    extern __shared__ uint32_t smw[];
    float* zS = (float*)smw;           // [8 w][ZROW] (after U-build phase)

    const int bx = blockIdx.x;
    const int tid = threadIdx.x;
    const int w = tid >> 5;
    const int lane = tid & 31;
    const int g = lane >> 2;
    const int t4 = lane & 3;

    // ---- one-time: build U B-fragments in registers (transient smem chunks)
    uint32_t uh[8][4][2], ul[8][4][2];
    {
        uint32_t* ubh = smw;
        uint32_t* ubl = smw + 32 * UBROW;
        for (int ch = 0; ch < 2; ++ch) {
            __syncthreads();
            for (int i = tid; i < 2048; i += NTHR) {
                int kp = i >> 3;
                int c4 = (i & 7) * 4;
                int gg = c4 >> 3, jj = c4 & 7;
                int gcol = gg * HH + bx * 8 + jj;
                int k0 = (ch * 256 + kp) * 2;
                float4 v0 = *(const float4*)(U + (size_t)k0 * G4H + gcol);
                float4 v1 = *(const float4*)(U + (size_t)(k0 + 1) * G4H + gcol);
                const float a0[4] = {v0.x, v0.y, v0.z, v0.w};
                const float a1[4] = {v1.x, v1.y, v1.z, v1.w};
#pragma unroll
                for (int q = 0; q < 4; ++q) {
                    float h0 = bfhi(a0[q]), l0 = a0[q] - h0;
                    float h1 = bfhi(a1[q]), l1 = a1[q] - h1;
                    ubh[(c4 + q) * UBROW + kp] = packbf2(h0, h1);
                    ubl[(c4 + q) * UBROW + kp] = packbf2(l0, l1);
                }
            }
            __syncthreads();
#pragma unroll
            for (int rr = 0; rr < 4; ++rr) {
                int r = ch * 4 + rr;
                int s = w + r * 8;
                int kwl = s * 8 - ch * 256;
#pragma unroll
                for (int nt = 0; nt < 4; ++nt) {
                    int ub = (nt * 8 + g) * UBROW + kwl + t4;
                    uh[r][nt][0] = ubh[ub];
                    uh[r][nt][1] = ubh[ub + 4];
                    ul[r][nt][0] = ubl[ub];
                    ul[r][nt][1] = ubl[ub + 4];
                }
            }
        }
        __syncthreads();
    }

    // ---- cell state: thread owns (om, oj)
    const int om = tid >> 3;
    const int oj = tid & 7;
    const int ohcol = bx * 8 + oj;
    float creg = g_c[om * HH + ohcol];

    volatile int* flags = (volatile int*)g_flag;

    for (int t = 0; t < TT; ++t) {
        float xw[4];
        {
            const float* xwp = g_xW + (size_t)(om * TT + t) * G4H + ohcol;
#pragma unroll
            for (int gg = 0; gg < 4; ++gg) xw[gg] = xwp[gg * HH];
        }

        const uint32_t* Hsrc = &g_hbf[t & 1][0][0][0];
        const uint32_t* Lsrc = &g_hbf[t & 1][1][0][0];

        float acc[2][4][4];
#pragma unroll
        for (int mt = 0; mt < 2; ++mt)
#pragma unroll
            for (int nt = 0; nt < 4; ++nt)
#pragma unroll
                for (int r = 0; r < 4; ++r) acc[mt][nt][r] = 0.f;

        uint32_t ah[2][2][4], al[2][2][4];   // [buf][mt][reg]

        {
            const int s = w;
            if (lane < 2) { while (flags[2 * s + lane] < t) { } }
            __syncwarp();
#pragma unroll
            for (int mt = 0; mt < 2; ++mt) {
                int base = (mt * 16 + g) * KP + s * 8 + t4;
                ah[0][mt][0] = Hsrc[base];
                ah[0][mt][1] = Hsrc[base + 8 * KP];
                ah[0][mt][2] = Hsrc[base + 4];
                ah[0][mt][3] = Hsrc[base + 8 * KP + 4];
                al[0][mt][0] = Lsrc[base];
                al[0][mt][1] = Lsrc[base + 8 * KP];
                al[0][mt][2] = Lsrc[base + 4];
                al[0][mt][3] = Lsrc[base + 8 * KP + 4];
            }
        }

#pragma unroll
        for (int r = 0; r < 8; ++r) {
            const int cur = r & 1;
            if (r < 7) {
                const int s = w + (r + 1) * 8;
                if (lane < 2) { while (flags[2 * s + lane] < t) { } }
                __syncwarp();
                const int nxt = cur ^ 1;
#pragma unroll
                for (int mt = 0; mt < 2; ++mt) {
                    int base = (mt * 16 + g) * KP + s * 8 + t4;
                    ah[nxt][mt][0] = Hsrc[base];
                    ah[nxt][mt][1] = Hsrc[base + 8 * KP];
                    ah[nxt][mt][2] = Hsrc[base + 4];
                    ah[nxt][mt][3] = Hsrc[base + 8 * KP + 4];
                    al[nxt][mt][0] = Lsrc[base];
                    al[nxt][mt][1] = Lsrc[base + 8 * KP];
                    al[nxt][mt][2] = Lsrc[base + 4];
                    al[nxt][mt][3] = Lsrc[base + 8 * KP + 4];
                }
            }
#pragma unroll
            for (int mt = 0; mt < 2; ++mt)
#pragma unroll
                for (int nt = 0; nt < 4; ++nt) {
                    mma_bf16(acc[mt][nt], ah[cur][mt][0], ah[cur][mt][1], ah[cur][mt][2], ah[cur][mt][3],
                             uh[r][nt][0], uh[r][nt][1]);
                    mma_bf16(acc[mt][nt], al[cur][mt][0], al[cur][mt][1], al[cur][mt][2], al[cur][mt][3],
                             uh[r][nt][0], uh[r][nt][1]);
                    mma_bf16(acc[mt][nt], ah[cur][mt][0], ah[cur][mt][1], ah[cur][mt][2], ah[cur][mt][3],
                             ul[r][nt][0], ul[r][nt][1]);
                }
        }

        __syncthreads();
#pragma unroll
        for (int mt = 0; mt < 2; ++mt)
#pragma unroll
            for (int nt = 0; nt < 4; ++nt) {
                int m = mt * 16 + g;
                int n = nt * 8 + t4 * 2;
                *(float2*)(zS + w * ZROW + m * 36 + n) = make_float2(acc[mt][nt][0], acc[mt][nt][1]);
                *(float2*)(zS + w * ZROW + (m + 8) * 36 + n) = make_float2(acc[mt][nt][2], acc[mt][nt][3]);
            }
        __syncthreads();

        float hn;
        {
            float z[4];
#pragma unroll
            for (int gi = 0; gi < 4; ++gi) {
                float s = 0.f;
#pragma unroll
                for (int w2 = 0; w2 < 8; ++w2)
                    s += zS[w2 * ZROW + om * 36 + gi * 8 + oj];
                z[gi] = s + xw[gi];
            }
            float si = 1.f / (1.f + expf(-z[0]));
            float sf = 1.f / (1.f + expf(-z[1]));
            float tg = tanhf(z[2]);
            float so = 1.f / (1.f + expf(-z[3]));
            creg = sf * creg + si * tg;
            hn = so * tanhf(creg);
        }

        {
            float hh = bfhi(hn), hl = hn - hh;
            float ph = __shfl_xor_sync(0xffffffffu, hh, 1);
            float pl = __shfl_xor_sync(0xffffffffu, hl, 1);
            if (!(oj & 1)) {
                int kp = bx * 4 + (oj >> 1);
                uint32_t wh = packbf2(hh, ph);
                uint32_t wl = packbf2(hl, pl);
                g_hbf[(t + 1) & 1][0][om][kp] = wh;
                g_hbf[(t + 1) & 1][1][om][kp] = wl;
                size_t row = (size_t)om * TT + t;
                g_sqh[row * KP + kp] = wh;
                g_sql[row * KP + kp] = wl;
            }
            if (t == TT - 1) g_h[0][om * HH + ohcol] = hn;
        }
        __threadfence();
        __syncthreads();
        if (tid == 0) flags[bx] = t + 1;
    }

    g_c[om * HH + ohcol] = creg;
}

// ---------------- launch ----------------
extern "C" void kernel_launch(void* const* d_in, const int* in_sizes, int n_in,
                              void* d_out, int out_size)
{
    const int*   x       = (const int*)d_in[0];
    const float* state_h = (const float*)d_in[1];
    const float* state_c = (const float*)d_in[2];
    const float* emb     = (const float*)d_in[3];
    const float* W       = (const float*)d_in[4];
    const float* U       = (const float*)d_in[5];
    const float* b       = (const float*)d_in[6];
    const float* dW      = (const float*)d_in[7];
    const float* db      = (const float*)d_in[8];
    float* out = (float*)d_out;

    float*    xW_ptr  = nullptr;
    uint32_t* sqh_ptr = nullptr;
    uint32_t* sql_ptr = nullptr;
    uint32_t* bhp_ptr = nullptr;
    uint32_t* blp_ptr = nullptr;
    cudaGetSymbolAddress((void**)&xW_ptr,  g_xW);
    cudaGetSymbolAddress((void**)&sqh_ptr, g_sqh);
    cudaGetSymbolAddress((void**)&sql_ptr, g_sql);
    cudaGetSymbolAddress((void**)&bhp_ptr, g_Bhp);
    cudaGetSymbolAddress((void**)&blp_ptr, g_Blp);

    // unconditional (no static guards); idempotent + capture-safe
    cudaFuncSetAttribute(lstm_scan_kernel,
                         cudaFuncAttributeMaxDynamicSharedMemorySize, SCAN_SMEM_BYTES);
    cudaFuncSetAttribute(bf16_gemm_kernel,
                         cudaFuncAttributeMaxDynamicSharedMemorySize, GEMM_SMEM_BYTES);

    // 1) load initial state (incl. packed bf16 h0) + reset flags
    init_state_kernel<<<64, 512>>>(state_h, state_c);

    // 1b) pre-split dense_W into packed bf16 hi/lo (pure streaming)
    split_b_kernel<<<8192, 256>>>(dW);

    // 2) xW = emb_table[x] @ W + b   (M=2048, N=4096, K=512, gathered A, fp32)
    {
        dim3 grid(G4H / 128, NROWS / 128);
        sgemm_kernel<true><<<grid, 256>>>(emb, x, W, b, xW_ptr, NROWS, G4H, EE, EE);
    }

    // 3) LSTM scan: persistent dataflow kernel (pipelined slice loads)
    lstm_scan_kernel<<<NBLK, NTHR, SCAN_SMEM_BYTES>>>(U);

    // 4) logits = seq @ dense_W + dense_b  (bf16x3, 2 blocks/SM, ldmatrix A)
    {
        dim3 grid(NROWS / 128, VV / 128);
        bf16_gemm_kernel<<<grid, 256, GEMM_SMEM_BYTES>>>(
            sqh_ptr, sql_ptr, bhp_ptr, blp_ptr, db, out, NROWS, VV, HH);
    }

    // 5) final h, c appended after logits
    float* out_h = out + (size_t)NROWS * VV;       // 65,536,000
    float* out_c = out_h + BB * HH;                // +32,768
    write_state_kernel<<<64, 512>>>(out_h, out_c);
}

// round 17
// speedup vs baseline: 1.6018x; 1.0179x over previous
#include <cuda_runtime.h>
#include <cuda_bf16.h>
#include <math.h>
#include <stdint.h>

// Problem constants
#define VV 32000
#define EE 512
#define HH 1024
#define BB 32
#define TT 64
#define G4H (4 * HH)          // 4096
#define NROWS (BB * TT)       // 2048
#define KP 512                // packed k-pairs per row (HH/2)
#define EKP 256               // packed k-pairs for E=512

#define NBLK 128              // persistent scan blocks
#define NTHR 256              // 8 warps

// scan smem (words): U-build transient (2*32*260) unions with zS (8*1156)
#define UBROW 260
#define ZROW 1156
#define SCAN_SMEM_WORDS (2*32*UBROW)
#define SCAN_SMEM_BYTES (SCAN_SMEM_WORDS * 4)   // 66,560 B

// GEMM smem word offsets (double-buffered -> 2 blocks/SM)
#define GA_H 0                // [2][2560]
#define GA_L 5120             // [2][2560]
#define GB_H 10240            // [2][2176]
#define GB_L 14592            // [2][2176]
#define GEMM_SMEM_WORDS 18944
#define GEMM_SMEM_BYTES (GEMM_SMEM_WORDS * 4)   // 75,776 B  (x2 = 151,552 <= 227KB)

// ---------------- scratch (no allocs allowed) ----------------
__device__ float    g_xW[NROWS * G4H];        // [b*T+t, 4H] input projections (+bias)
__device__ uint32_t g_sqh[(size_t)NROWS * KP];// seq packed bf16 hi pairs [row][kp]
__device__ uint32_t g_sql[(size_t)NROWS * KP];// seq packed bf16 lo pairs
__device__ float    g_h[2][BB * HH];          // final-h staging
__device__ float    g_c[BB * HH];             // cell state
__device__ int      g_flag[NBLK];             // per-block publish counters
__device__ uint32_t g_hbf[2][2][32][KP];      // packed bf16 h pairs [buf][hi/lo][m][kp]
__device__ uint32_t g_Bhp[(size_t)KP * VV];   // dense_W packed bf16 hi pairs [kp][n]
__device__ uint32_t g_Blp[(size_t)KP * VV];   // dense_W packed bf16 lo pairs
__device__ uint32_t g_Wh[(size_t)EKP * G4H];  // W packed bf16 hi pairs [kp][n]
__device__ uint32_t g_Wl[(size_t)EKP * G4H];  // W packed bf16 lo pairs
__device__ uint32_t g_xqh[(size_t)NROWS * EKP]; // gathered emb packed hi [row][kp]
__device__ uint32_t g_xql[(size_t)NROWS * EKP]; // gathered emb packed lo

// ---------------- helpers ----------------
__device__ __forceinline__ uint32_t packbf2(float a, float b) {  // a -> low half (k even)
    __nv_bfloat162 p = __floats2bfloat162_rn(a, b);
    return *reinterpret_cast<uint32_t*>(&p);
}
__device__ __forceinline__ float bfhi(float x) {
    return __bfloat162float(__float2bfloat16_rn(x));
}
__device__ __forceinline__ void mma_bf16(float* c, uint32_t a0, uint32_t a1, uint32_t a2, uint32_t a3,
                                         uint32_t b0, uint32_t b1) {
    asm volatile(
        "mma.sync.aligned.m16n8k16.row.col.f32.bf16.bf16.f32 "
        "{%0,%1,%2,%3}, {%4,%5,%6,%7}, {%8,%9}, {%0,%1,%2,%3};"
        : "+f"(c[0]), "+f"(c[1]), "+f"(c[2]), "+f"(c[3])
        : "r"(a0), "r"(a1), "r"(a2), "r"(a3), "r"(b0), "r"(b1));
}
__device__ __forceinline__ void ldsm4(uint32_t* r, uint32_t addr) {
    asm volatile("ldmatrix.sync.aligned.m8n8.x4.shared.b16 {%0,%1,%2,%3}, [%4];"
        : "=r"(r[0]), "=r"(r[1]), "=r"(r[2]), "=r"(r[3]) : "r"(addr));
}
__device__ __forceinline__ void cp16(uint32_t smem_addr, const void* gmem) {
    asm volatile("cp.async.cg.shared.global [%0], [%1], 16;" :: "r"(smem_addr), "l"(gmem) : "memory");
}
#define CP_COMMIT asm volatile("cp.async.commit_group;" ::: "memory")
#define CP_WAIT0  asm volatile("cp.async.wait_group 0;" ::: "memory")
#define CP_WAIT1  asm volatile("cp.async.wait_group 1;" ::: "memory")

__device__ __forceinline__ void st_release_gpu(int* p, int v) {
    asm volatile("st.release.gpu.global.b32 [%0], %1;" :: "l"(p), "r"(v) : "memory");
}
__device__ __forceinline__ int ld_acquire_gpu(const int* p) {
    int v;
    asm volatile("ld.acquire.gpu.global.b32 %0, [%1];" : "=r"(v) : "l"(p) : "memory");
    return v;
}

// ---------------- init / finalize ----------------
__global__ void init_state_kernel(const float* __restrict__ h0, const float* __restrict__ c0) {
    int i = blockIdx.x * blockDim.x + threadIdx.x;
    if (i < BB * HH) g_c[i] = c0[i];
    if (i < BB * HH / 2) {                 // pack h0 into g_hbf[0]
        int m = i >> 9;
        int kp = i & 511;
        float a = h0[m * HH + 2 * kp];
        float b = h0[m * HH + 2 * kp + 1];
        float ah = bfhi(a), bh = bfhi(b);
        g_hbf[0][0][m][kp] = packbf2(ah, bh);
        g_hbf[0][1][m][kp] = packbf2(a - ah, b - bh);
    }
    if (i < NBLK) g_flag[i] = 0;
}

__global__ void write_state_kernel(float* __restrict__ out_h, float* __restrict__ out_c) {
    int i = blockIdx.x * blockDim.x + threadIdx.x;
    if (i < BB * HH) {
        out_h[i] = g_h[0][i];
        out_c[i] = g_c[i];
    }
}

// ---------------- generic fp32 -> packed bf16 hi/lo [kp][n] splitter ----------------
__global__ void split_pack_kernel(const float* __restrict__ B,
                                  uint32_t* __restrict__ Hd, uint32_t* __restrict__ Ld,
                                  int kprows, int N)
{
    const size_t tot = (size_t)kprows * (N / 4);
    size_t idx = (size_t)blockIdx.x * blockDim.x + threadIdx.x;
    const size_t stride = (size_t)gridDim.x * blockDim.x;
    for (; idx < tot; idx += stride) {
        int kp = (int)(idx / (N / 4));
        int n4 = (int)(idx % (N / 4)) * 4;
        float4 v0 = *(const float4*)(B + (size_t)(2 * kp) * N + n4);
        float4 v1 = *(const float4*)(B + (size_t)(2 * kp + 1) * N + n4);
        uint4 ho, lo;
        {
            float h0 = bfhi(v0.x), h1 = bfhi(v1.x);
            ho.x = packbf2(h0, h1); lo.x = packbf2(v0.x - h0, v1.x - h1);
        }
        {
            float h0 = bfhi(v0.y), h1 = bfhi(v1.y);
            ho.y = packbf2(h0, h1); lo.y = packbf2(v0.y - h0, v1.y - h1);
        }
        {
            float h0 = bfhi(v0.z), h1 = bfhi(v1.z);
            ho.z = packbf2(h0, h1); lo.z = packbf2(v0.z - h0, v1.z - h1);
        }
        {
            float h0 = bfhi(v0.w), h1 = bfhi(v1.w);
            ho.w = packbf2(h0, h1); lo.w = packbf2(v0.w - h0, v1.w - h1);
        }
        *(uint4*)(Hd + (size_t)kp * N + n4) = ho;
        *(uint4*)(Ld + (size_t)kp * N + n4) = lo;
    }
}

// ---------------- embedding gather + bf16 hi/lo pack (A for xW GEMM) ----------------
__global__ void gather_split_emb_kernel(const int* __restrict__ x,
                                        const float* __restrict__ emb)
{
    int idx = blockIdx.x * blockDim.x + threadIdx.x;   // 0 .. NROWS*EKP-1
    if (idx >= NROWS * EKP) return;
    int r = idx >> 8;          // row (b*T + t)
    int kp = idx & (EKP - 1);
    const float2 v = *(const float2*)(emb + (size_t)x[r] * EE + 2 * kp);
    float ah = bfhi(v.x), bh = bfhi(v.y);
    g_xqh[(size_t)r * EKP + kp] = packbf2(ah, bh);
    g_xql[(size_t)r * EKP + kp] = packbf2(v.x - ah, v.y - bh);
}

// ---------------- bf16x3 GEMM: 2 blocks/SM + ldmatrix A frags ----------------
// Grid: (M/128 fast, N/128 slow). Double-buffered cp.async. K%32==0.
__global__ __launch_bounds__(256, 2)
void bf16_gemm_kernel(const uint32_t* __restrict__ Ahp, const uint32_t* __restrict__ Alp,
                      const uint32_t* __restrict__ Bhp, const uint32_t* __restrict__ Blp,
                      const float* __restrict__ bias, float* __restrict__ C,
                      int M, int N, int K)
{
    extern __shared__ uint32_t gsm[];
    const int tid = threadIdx.x;
    const int lane = tid & 31, wid = tid >> 5;
    const int wr = wid >> 2, wc = wid & 3;
    const int g = lane >> 2, t4 = lane & 3;
    const int bm = blockIdx.x * 128, bn = blockIdx.y * 128;   // bm = FAST axis
    const int kprow = K >> 1;
    const uint32_t smB = (uint32_t)__cvta_generic_to_shared(gsm);

    const int lrow = lane & 15;
    const int lcol = (lane >> 4) * 4;

    float acc[4][4][4];
#pragma unroll
    for (int i = 0; i < 4; ++i)
#pragma unroll
        for (int j = 0; j < 4; ++j)
#pragma unroll
            for (int r = 0; r < 4; ++r) acc[i][j][r] = 0.f;

    const int ntiles = K / 32;

    auto issue = [&](int tile, int buf) {
        int ktp = tile * 16;
#pragma unroll
        for (int i = 0; i < 2; ++i) {
            int id = tid + i * 256;
            int m = id >> 2, kp4 = id & 3;
            const uint32_t* sH = Ahp + (size_t)(bm + m) * kprow + ktp + kp4 * 4;
            const uint32_t* sL = Alp + (size_t)(bm + m) * kprow + ktp + kp4 * 4;
            cp16(smB + (GA_H + buf * 2560 + m * 20 + kp4 * 4) * 4, sH);
            cp16(smB + (GA_L + buf * 2560 + m * 20 + kp4 * 4) * 4, sL);
        }
#pragma unroll
        for (int i = 0; i < 2; ++i) {
            int id = tid + i * 256;
            int kr = id >> 5, n4 = (id & 31) * 4;
            const uint32_t* sH = Bhp + (size_t)(ktp + kr) * N + bn + n4;
            const uint32_t* sL = Blp + (size_t)(ktp + kr) * N + bn + n4;
            cp16(smB + (GB_H + buf * 2176 + kr * 136 + n4) * 4, sH);
            cp16(smB + (GB_L + buf * 2176 + kr * 136 + n4) * 4, sL);
        }
        CP_COMMIT;
    };

    issue(0, 0);
    for (int tile = 0; tile < ntiles; ++tile) {
        int buf = tile & 1;
        if (tile + 1 < ntiles) { issue(tile + 1, buf ^ 1); CP_WAIT1; }
        else                   { CP_WAIT0; }
        __syncthreads();

        const uint32_t baseAH = GA_H + buf * 2560;
        const uint32_t baseAL = GA_L + buf * 2560;
        const uint32_t* BhT = gsm + GB_H + buf * 2176;
        const uint32_t* BlT = gsm + GB_L + buf * 2176;
#pragma unroll
        for (int s = 0; s < 2; ++s) {
            const int kwb = s * 8;
            const int kb = kwb + t4;
            uint32_t ah[4][4], al[4][4];
#pragma unroll
            for (int mt = 0; mt < 4; ++mt) {
                uint32_t roff = (uint32_t)((wr * 64 + mt * 16 + lrow) * 20 + kwb + lcol);
                ldsm4(ah[mt], smB + (baseAH + roff) * 4);
                ldsm4(al[mt], smB + (baseAL + roff) * 4);
            }
#pragma unroll
            for (int nt = 0; nt < 4; ++nt) {
                int c0 = wc * 32 + nt * 8 + g;
                uint32_t bh0 = BhT[kb * 136 + c0];
                uint32_t bh1 = BhT[(kb + 4) * 136 + c0];
                uint32_t bl0 = BlT[kb * 136 + c0];
                uint32_t bl1 = BlT[(kb + 4) * 136 + c0];
#pragma unroll
                for (int mt = 0; mt < 4; ++mt) {
                    mma_bf16(acc[mt][nt], ah[mt][0], ah[mt][1], ah[mt][2], ah[mt][3], bh0, bh1);
                    mma_bf16(acc[mt][nt], al[mt][0], al[mt][1], al[mt][2], al[mt][3], bh0, bh1);
                    mma_bf16(acc[mt][nt], ah[mt][0], ah[mt][1], ah[mt][2], ah[mt][3], bl0, bl1);
                }
            }
        }
        __syncthreads();
    }

#pragma unroll
    for (int mt = 0; mt < 4; ++mt) {
        int r0 = bm + wr * 64 + mt * 16 + g;
#pragma unroll
        for (int nt = 0; nt < 4; ++nt) {
            int col = bn + wc * 32 + nt * 8 + 2 * t4;
            float b0 = bias[col], b1 = bias[col + 1];
            float2 v0 = make_float2(acc[mt][nt][0] + b0, acc[mt][nt][1] + b1);
            float2 v1 = make_float2(acc[mt][nt][2] + b0, acc[mt][nt][3] + b1);
            *(float2*)(C + (size_t)r0 * N + col) = v0;
            *(float2*)(C + (size_t)(r0 + 8) * N + col) = v1;
        }
    }
}

// ---------------- persistent LSTM scan (bf16x3 TC, dataflow, release/acquire) ----------------
__global__ __launch_bounds__(NTHR, 1)
void lstm_scan_kernel(const float* __restrict__ U)
{
    extern __shared__ uint32_t smw[];
    float* zS = (float*)smw;           // [8 w][ZROW] (after U-build phase)

    const int bx = blockIdx.x;
    const int tid = threadIdx.x;
    const int w = tid >> 5;
    const int lane = tid & 31;
    const int g = lane >> 2;
    const int t4 = lane & 3;

    // ---- one-time: build U B-fragments in registers (transient smem chunks)
    uint32_t uh[8][4][2], ul[8][4][2];
    {
        uint32_t* ubh = smw;
        uint32_t* ubl = smw + 32 * UBROW;
        for (int ch = 0; ch < 2; ++ch) {
            __syncthreads();
            for (int i = tid; i < 2048; i += NTHR) {
                int kp = i >> 3;
                int c4 = (i & 7) * 4;
                int gg = c4 >> 3, jj = c4 & 7;
                int gcol = gg * HH + bx * 8 + jj;
                int k0 = (ch * 256 + kp) * 2;
                float4 v0 = *(const float4*)(U + (size_t)k0 * G4H + gcol);
                float4 v1 = *(const float4*)(U + (size_t)(k0 + 1) * G4H + gcol);
                const float a0[4] = {v0.x, v0.y, v0.z, v0.w};
                const float a1[4] = {v1.x, v1.y, v1.z, v1.w};
#pragma unroll
                for (int q = 0; q < 4; ++q) {
                    float h0 = bfhi(a0[q]), l0 = a0[q] - h0;
                    float h1 = bfhi(a1[q]), l1 = a1[q] - h1;
                    ubh[(c4 + q) * UBROW + kp] = packbf2(h0, h1);
                    ubl[(c4 + q) * UBROW + kp] = packbf2(l0, l1);
                }
            }
            __syncthreads();
#pragma unroll
            for (int rr = 0; rr < 4; ++rr) {
                int r = ch * 4 + rr;
                int s = w + r * 8;
                int kwl = s * 8 - ch * 256;
#pragma unroll
                for (int nt = 0; nt < 4; ++nt) {
                    int ub = (nt * 8 + g) * UBROW + kwl + t4;
                    uh[r][nt][0] = ubh[ub];
                    uh[r][nt][1] = ubh[ub + 4];
                    ul[r][nt][0] = ubl[ub];
                    ul[r][nt][1] = ubl[ub + 4];
                }
            }
        }
        __syncthreads();
    }

    // ---- cell state: thread owns (om, oj)
    const int om = tid >> 3;
    const int oj = tid & 7;
    const int ohcol = bx * 8 + oj;
    float creg = g_c[om * HH + ohcol];

    for (int t = 0; t < TT; ++t) {
        float xw[4];
        {
            const float* xwp = g_xW + (size_t)(om * TT + t) * G4H + ohcol;
#pragma unroll
            for (int gg = 0; gg < 4; ++gg) xw[gg] = xwp[gg * HH];
        }

        const uint32_t* Hsrc = &g_hbf[t & 1][0][0][0];
        const uint32_t* Lsrc = &g_hbf[t & 1][1][0][0];

        float acc[2][4][4];
#pragma unroll
        for (int mt = 0; mt < 2; ++mt)
#pragma unroll
            for (int nt = 0; nt < 4; ++nt)
#pragma unroll
                for (int r = 0; r < 4; ++r) acc[mt][nt][r] = 0.f;

        uint32_t ah[2][2][4], al[2][2][4];   // [buf][mt][reg]

        {
            const int s = w;
            if (lane < 2) { while (ld_acquire_gpu(&g_flag[2 * s + lane]) < t) { } }
            __syncwarp();
#pragma unroll
            for (int mt = 0; mt < 2; ++mt) {
                int base = (mt * 16 + g) * KP + s * 8 + t4;
                ah[0][mt][0] = Hsrc[base];
                ah[0][mt][1] = Hsrc[base + 8 * KP];
                ah[0][mt][2] = Hsrc[base + 4];
                ah[0][mt][3] = Hsrc[base + 8 * KP + 4];
                al[0][mt][0] = Lsrc[base];
                al[0][mt][1] = Lsrc[base + 8 * KP];
                al[0][mt][2] = Lsrc[base + 4];
                al[0][mt][3] = Lsrc[base + 8 * KP + 4];
            }
        }

#pragma unroll
        for (int r = 0; r < 8; ++r) {
            const int cur = r & 1;
            if (r < 7) {
                const int s = w + (r + 1) * 8;
                if (lane < 2) { while (ld_acquire_gpu(&g_flag[2 * s + lane]) < t) { } }
                __syncwarp();
                const int nxt = cur ^ 1;
#pragma unroll
                for (int mt = 0; mt < 2; ++mt) {
                    int base = (mt * 16 + g) * KP + s * 8 + t4;
                    ah[nxt][mt][0] = Hsrc[base];
                    ah[nxt][mt][1] = Hsrc[base + 8 * KP];
                    ah[nxt][mt][2] = Hsrc[base + 4];
                    ah[nxt][mt][3] = Hsrc[base + 8 * KP + 4];
                    al[nxt][mt][0] = Lsrc[base];
                    al[nxt][mt][1] = Lsrc[base + 8 * KP];
                    al[nxt][mt][2] = Lsrc[base + 4];
                    al[nxt][mt][3] = Lsrc[base + 8 * KP + 4];
                }
            }
#pragma unroll
            for (int mt = 0; mt < 2; ++mt)
#pragma unroll
                for (int nt = 0; nt < 4; ++nt) {
                    mma_bf16(acc[mt][nt], ah[cur][mt][0], ah[cur][mt][1], ah[cur][mt][2], ah[cur][mt][3],
                             uh[r][nt][0], uh[r][nt][1]);
                    mma_bf16(acc[mt][nt], al[cur][mt][0], al[cur][mt][1], al[cur][mt][2], al[cur][mt][3],
                             uh[r][nt][0], uh[r][nt][1]);
                    mma_bf16(acc[mt][nt], ah[cur][mt][0], ah[cur][mt][1], ah[cur][mt][2], ah[cur][mt][3],
                             ul[r][nt][0], ul[r][nt][1]);
                }
        }

        __syncthreads();
#pragma unroll
        for (int mt = 0; mt < 2; ++mt)
#pragma unroll
            for (int nt = 0; nt < 4; ++nt) {
                int m = mt * 16 + g;
                int n = nt * 8 + t4 * 2;
                *(float2*)(zS + w * ZROW + m * 36 + n) = make_float2(acc[mt][nt][0], acc[mt][nt][1]);
                *(float2*)(zS + w * ZROW + (m + 8) * 36 + n) = make_float2(acc[mt][nt][2], acc[mt][nt][3]);
            }
        __syncthreads();

        float hn;
        {
            float z[4];
#pragma unroll
            for (int gi = 0; gi < 4; ++gi) {
                float s = 0.f;
#pragma unroll
                for (int w2 = 0; w2 < 8; ++w2)
                    s += zS[w2 * ZROW + om * 36 + gi * 8 + oj];
                z[gi] = s + xw[gi];
            }
            float si = 1.f / (1.f + expf(-z[0]));
            float sf = 1.f / (1.f + expf(-z[1]));
            float tg = tanhf(z[2]);
            float so = 1.f / (1.f + expf(-z[3]));
            creg = sf * creg + si * tg;
            hn = so * tanhf(creg);
        }

        {
            float hh = bfhi(hn), hl = hn - hh;
            float ph = __shfl_xor_sync(0xffffffffu, hh, 1);
            float pl = __shfl_xor_sync(0xffffffffu, hl, 1);
            if (!(oj & 1)) {
                int kp = bx * 4 + (oj >> 1);
                uint32_t wh = packbf2(hh, ph);
                uint32_t wl = packbf2(hl, pl);
                g_hbf[(t + 1) & 1][0][om][kp] = wh;
                g_hbf[(t + 1) & 1][1][om][kp] = wl;
                size_t row = (size_t)om * TT + t;
                g_sqh[row * KP + kp] = wh;
                g_sql[row * KP + kp] = wl;
            }
            if (t == TT - 1) g_h[0][om * HH + ohcol] = hn;
        }
        // publish: block-wide sync gives happens-before into tid0's release store
        __syncthreads();
        if (tid == 0) st_release_gpu(&g_flag[bx], t + 1);
    }

    g_c[om * HH + ohcol] = creg;
}

// ---------------- launch ----------------
extern "C" void kernel_launch(void* const* d_in, const int* in_sizes, int n_in,
                              void* d_out, int out_size)
{
    const int*   x       = (const int*)d_in[0];
    const float* state_h = (const float*)d_in[1];
    const float* state_c = (const float*)d_in[2];
    const float* emb     = (const float*)d_in[3];
    const float* W       = (const float*)d_in[4];
    const float* U       = (const float*)d_in[5];
    const float* b       = (const float*)d_in[6];
    const float* dW      = (const float*)d_in[7];
    const float* db      = (const float*)d_in[8];
    float* out = (float*)d_out;

    float*    xW_ptr  = nullptr;
    uint32_t* sqh_ptr = nullptr;
    uint32_t* sql_ptr = nullptr;
    uint32_t* bhp_ptr = nullptr;
    uint32_t* blp_ptr = nullptr;
    uint32_t* wh_ptr  = nullptr;
    uint32_t* wl_ptr  = nullptr;
    uint32_t* xqh_ptr = nullptr;
    uint32_t* xql_ptr = nullptr;
    cudaGetSymbolAddress((void**)&xW_ptr,  g_xW);
    cudaGetSymbolAddress((void**)&sqh_ptr, g_sqh);
    cudaGetSymbolAddress((void**)&sql_ptr, g_sql);
    cudaGetSymbolAddress((void**)&bhp_ptr, g_Bhp);
    cudaGetSymbolAddress((void**)&blp_ptr, g_Blp);
    cudaGetSymbolAddress((void**)&wh_ptr,  g_Wh);
    cudaGetSymbolAddress((void**)&wl_ptr,  g_Wl);
    cudaGetSymbolAddress((void**)&xqh_ptr, g_xqh);
    cudaGetSymbolAddress((void**)&xql_ptr, g_xql);

    // unconditional (no static guards); idempotent + capture-safe
    cudaFuncSetAttribute(lstm_scan_kernel,
                         cudaFuncAttributeMaxDynamicSharedMemorySize, SCAN_SMEM_BYTES);
    cudaFuncSetAttribute(bf16_gemm_kernel,
                         cudaFuncAttributeMaxDynamicSharedMemorySize, GEMM_SMEM_BYTES);

    // 1) load initial state (incl. packed bf16 h0) + reset flags
    init_state_kernel<<<64, 512>>>(state_h, state_c);

    // 1b) pre-split dense_W and W into packed bf16 hi/lo; gather+split embeddings
    split_pack_kernel<<<8192, 256>>>(dW, bhp_ptr, blp_ptr, KP, VV);
    split_pack_kernel<<<1024, 256>>>(W, wh_ptr, wl_ptr, EKP, G4H);
    gather_split_emb_kernel<<<NROWS * EKP / 256, 256>>>(x, emb);

    // 2) xW = emb_table[x] @ W + b   (bf16x3 tensor cores; M=2048, N=4096, K=512)
    {
        dim3 grid(NROWS / 128, G4H / 128);
        bf16_gemm_kernel<<<grid, 256, GEMM_SMEM_BYTES>>>(
            xqh_ptr, xql_ptr, wh_ptr, wl_ptr, b, xW_ptr, NROWS, G4H, EE);
    }

    // 3) LSTM scan: persistent dataflow kernel (release/acquire flags)
    lstm_scan_kernel<<<NBLK, NTHR, SCAN_SMEM_BYTES>>>(U);

    // 4) logits = seq @ dense_W + dense_b  (bf16x3, 2 blocks/SM, ldmatrix A)
    {
        dim3 grid(NROWS / 128, VV / 128);
        bf16_gemm_kernel<<<grid, 256, GEMM_SMEM_BYTES>>>(
            sqh_ptr, sql_ptr, bhp_ptr, blp_ptr, db, out, NROWS, VV, HH);
    }

    // 5) final h, c appended after logits
    float* out_h = out + (size_t)NROWS * VV;       // 65,536,000
    float* out_c = out_h + BB * HH;                // +32,768
    write_state_kernel<<<64, 512>>>(out_h, out_c);
}